// round 11
// baseline (speedup 1.0000x reference)
#include <cuda_runtime.h>
#include <cstdint>

#define NB 2
#define NH 16
#define NS 2048
#define ND 64

// Scratch (allocation-free rule: __device__ globals)
// g_Q/g_K/g_V hold tf32-rounded bit patterns (Q pre-scaled by 1/8),
// produced by proj_kernel, consumed raw by attn (bit-identical to R5 math).
__device__ float g_Q[NB*NH*NS*ND];
__device__ float g_K[NB*NH*NS*ND];
__device__ float g_V[NB*NH*NS*ND];

// ---------------------------------------------------------------------------
// helpers
// ---------------------------------------------------------------------------
__device__ __forceinline__ uint32_t f2tf32(float x) {
    uint32_t r;
    asm("cvt.rna.tf32.f32 %0, %1;" : "=r"(r) : "f"(x));
    return r;
}
// m16n8k8 tf32 warp MMA, fp32 accumulate (base ISA, works on sm_103 target)
__device__ __forceinline__ void mma8(float* c, const uint32_t* a,
                                     uint32_t b0, uint32_t b1) {
    asm volatile(
        "mma.sync.aligned.m16n8k8.row.col.f32.tf32.tf32.f32 "
        "{%0,%1,%2,%3}, {%4,%5,%6,%7}, {%8,%9}, {%0,%1,%2,%3};"
        : "+f"(c[0]), "+f"(c[1]), "+f"(c[2]), "+f"(c[3])
        : "r"(a[0]), "r"(a[1]), "r"(a[2]), "r"(a[3]), "r"(b0), "r"(b1));
}
__device__ __forceinline__ uint32_t smem_u32(const void* p) {
    uint32_t a;
    asm("{ .reg .u64 t; cvta.to.shared.u64 t, %1; cvt.u32.u64 %0, t; }"
        : "=r"(a) : "l"(p));
    return a;
}
__device__ __forceinline__ void cpasync16(uint32_t dst, const void* src) {
    asm volatile("cp.async.cg.shared.global [%0], [%1], 16;"
                 :: "r"(dst), "l"(src));
}
#define CP_COMMIT() asm volatile("cp.async.commit_group;" ::: "memory")
#define CP_WAIT0()  asm volatile("cp.async.wait_group 0;" ::: "memory")

// ---------------------------------------------------------------------------
// JAX partitionable threefry2x32, key=(0,42): bits[i] = o0^o1, counter (0,i)
// R5 form (best measured). Executed between cp.async issue and wait so the
// ALU work hides the GMEM->SMEM latency.
// ---------------------------------------------------------------------------
__device__ __forceinline__ uint32_t rotl32(uint32_t x, int r) {
    return __funnelshift_l(x, x, r);
}
#define KEEP_THRESH 0xE6666600u   // uniform < 0.9f, exact integer reduction

// returns bit0 = keep(e), bit1 = keep(e+1); two interleaved ciphers for ILP
__device__ __forceinline__ uint32_t keep2(uint32_t e) {
    const uint32_t k0 = 0u, k1 = 42u, k2 = 0u ^ 42u ^ 0x1BD11BDAu;
    uint32_t a0 = k0, b0 = e + k1;
    uint32_t a1 = k0, b1 = e + 1u + k1;
#define TF_R2(r) { a0 += b0; b0 = rotl32(b0, (r)) ^ a0;                        \
                   a1 += b1; b1 = rotl32(b1, (r)) ^ a1; }
    TF_R2(13) TF_R2(15) TF_R2(26) TF_R2(6)
    a0 += k1; a1 += k1; b0 += k2 + 1u; b1 += k2 + 1u;
    TF_R2(17) TF_R2(29) TF_R2(16) TF_R2(24)
    a0 += k2; a1 += k2; b0 += k0 + 2u; b1 += k0 + 2u;
    TF_R2(13) TF_R2(15) TF_R2(26) TF_R2(6)
    a0 += k0; a1 += k0; b0 += k1 + 3u; b1 += k1 + 3u;
    TF_R2(17) TF_R2(29) TF_R2(16) TF_R2(24)
    a0 += k1; a1 += k1; b0 += k2 + 4u; b1 += k2 + 4u;
    TF_R2(13) TF_R2(15) TF_R2(26) TF_R2(6)
    a0 += k2; a1 += k2; b0 += k0 + 5u; b1 += k0 + 5u;
#undef TF_R2
    uint32_t r = ((a0 ^ b0) < KEEP_THRESH) ? 1u : 0u;
    r |= ((a1 ^ b1) < KEEP_THRESH) ? 2u : 0u;
    return r;
}

// ---------------------------------------------------------------------------
// QKV projection: Y = tf32_rna(X @ W^T + b), Q additionally scaled by 1/8.
// Output [B,H,S,D]. One launch, grid.y selects {Q,K,V}.
// ---------------------------------------------------------------------------
__global__ void proj_kernel(const float* __restrict__ Xq,
                            const float* __restrict__ Xk,
                            const float* __restrict__ Xv,
                            const float* __restrict__ Wq_,
                            const float* __restrict__ Wk_,
                            const float* __restrict__ Wv_,
                            const float* __restrict__ bq_,
                            const float* __restrict__ bk_,
                            const float* __restrict__ bv_) {
    __shared__ __align__(16) float Xt[64][68];
    __shared__ __align__(16) float Wt[64][68];
    __shared__ float bs[64];
    int which = blockIdx.y;
    const float* X = (which == 0) ? Xq : (which == 1) ? Xk : Xv;
    const float* W = (which == 0) ? Wq_ : (which == 1) ? Wk_ : Wv_;
    const float* bias = (which == 0) ? bq_ : (which == 1) ? bk_ : bv_;
    float* Y = (which == 0) ? g_Q : (which == 1) ? g_K : g_V;
    float scale = (which == 0) ? 0.125f : 1.0f;

    int tid = threadIdx.x;
    if (tid < 64) bs[tid] = bias[tid];
    int r0 = blockIdx.x * 64;

#pragma unroll
    for (int r = 0; r < 4; r++) {
        int fidx = tid + r * 256;
        int row = fidx >> 4, dg = fidx & 15;
        int pg = (((row >> 2) ^ dg) << 2) + (row & 3);
        float4 w4 = reinterpret_cast<const float4*>(W)[fidx];
        Wt[4*dg+0][pg] = w4.x; Wt[4*dg+1][pg] = w4.y;
        Wt[4*dg+2][pg] = w4.z; Wt[4*dg+3][pg] = w4.w;
        float4 x4 = reinterpret_cast<const float4*>(X + (size_t)(r0 + row) * 64)[dg];
        Xt[4*dg+0][pg] = x4.x; Xt[4*dg+1][pg] = x4.y;
        Xt[4*dg+2][pg] = x4.z; Xt[4*dg+3][pg] = x4.w;
    }
    __syncthreads();

    int ty = tid >> 4, tx = tid & 15;
    float acc[4][4] = {};
#pragma unroll 8
    for (int d = 0; d < 64; d++) {
        int sw = d >> 2;
        float4 xv = *reinterpret_cast<float4*>(&Xt[d][(ty ^ sw) << 2]);
        float4 wv = *reinterpret_cast<float4*>(&Wt[d][(tx ^ sw) << 2]);
        float xa[4] = {xv.x, xv.y, xv.z, xv.w};
        float wa[4] = {wv.x, wv.y, wv.z, wv.w};
#pragma unroll
        for (int i = 0; i < 4; i++)
#pragma unroll
            for (int j = 0; j < 4; j++) acc[i][j] += xa[i] * wa[j];
    }

#pragma unroll
    for (int i = 0; i < 4; i++) {
        int r = r0 + ty * 4 + i;
        int b = r >> 15;
        int rem = r & 32767;
        int s = rem >> 4, h = rem & 15;
        uint4 o;
        o.x = f2tf32((acc[i][0] + bs[tx*4+0]) * scale);
        o.y = f2tf32((acc[i][1] + bs[tx*4+1]) * scale);
        o.z = f2tf32((acc[i][2] + bs[tx*4+2]) * scale);
        o.w = f2tf32((acc[i][3] + bs[tx*4+3]) * scale);
        reinterpret_cast<uint4*>(Y + ((size_t)(b*NH + h)*NS + s)*ND)[tx] = o;
    }
}

// ---------------------------------------------------------------------------
// Warp-MMA (m16n8k8 tf32) flash attention with FUSED threefry dropout.
// Block: 64 queries x head x batch, 128 threads = 4 warps (16 q-rows each).
// SMEM (uint32): Ks [64][68], Vs [64][72], Ps [4 warps][16][68]
//                (Ps doubles as Q staging before the mainloop).
// R10 structure; launch_bounds (128,4) targets 4 blocks/SM (16 warps) --
// smem 53.2KB*4 = 213KB fits, registers are the knob (<=125 needed).
// ---------------------------------------------------------------------------
#define KS_OFF 0
#define VS_OFF 4352          /* 64*68 */
#define PS_OFF 8960          /* + 64*72 */
#define SMEM_WORDS 13312     /* + 4*16*68 */

__global__ __launch_bounds__(128, 4) void attn_mma_kernel(
        const float* __restrict__ mask, float* __restrict__ out) {
    extern __shared__ __align__(16) uint32_t sm[];
    uint32_t* Ks = sm + KS_OFF;
    uint32_t* Vs = sm + VS_OFF;
    uint32_t* Ps = sm + PS_OFF;
    uint32_t sb = smem_u32(sm);

    int tid = threadIdx.x;
    int lane = tid & 31, w = tid >> 5;       // 4 warps
    int gi = lane >> 2, ci = lane & 3;
    int qt = blockIdx.x, h = blockIdx.y, b = blockIdx.z;
    int bh = b * NH + h;
    int q0 = qt * 64;

    int row = tid >> 1, hf = tid & 1;        // staging: 64 rows x 2 halves

    // staging smem byte-addresses for this thread
    uint32_t ks_dst = sb + (KS_OFF + row * 68 + hf * 32) * 4;
    uint32_t vs_dst = sb + (VS_OFF + row * 72 + hf * 32) * 4;

    // ---- stage Q tile (already tf32+scaled) into Ps via cp.async ----
    {
        uint32_t ps_dst = sb + (PS_OFF + row * 68 + hf * 32) * 4;
        const float* Qg = g_Q + ((size_t)bh * NS + q0 + row) * ND + hf * 32;
#pragma unroll
        for (int j = 0; j < 8; j++)
            cpasync16(ps_dst + j * 16, Qg + j * 4);
        CP_COMMIT();
        CP_WAIT0();
    }
    __syncthreads();
    uint32_t qf[8][4];
    {
        const uint32_t* Qs = Ps + (w * 16) * 68;
#pragma unroll
        for (int kc = 0; kc < 8; kc++) {
            qf[kc][0] = Qs[gi * 68 + kc * 8 + ci];
            qf[kc][1] = Qs[(gi + 8) * 68 + kc * 8 + ci];
            qf[kc][2] = Qs[gi * 68 + kc * 8 + ci + 4];
            qf[kc][3] = Qs[(gi + 8) * 68 + kc * 8 + ci + 4];
        }
    }
    __syncthreads();   // Ps will be overwritten as P-buffer in the mainloop

    float oacc[8][4] = {};
    float m_lo = -3.0e38f, m_hi = -3.0e38f, l_lo = 0.f, l_hi = 0.f;

    int rlo = q0 + w * 16 + gi;              // rhi = rlo + 8 (derived)
    // single mask base; the hi row is a constant +8*NS floats away
    const float* mask_lo = mask + ((size_t)b * NS + rlo) * NS;
    // flat dropout-element base (hi base = lo + 8*NS, constant)
    uint32_t ebl = (uint32_t)(bh * NS + rlo) * NS + 2 * ci;

    // single K base; V derived per-use from separate global
    const float* Kbase = g_K + ((size_t)bh * NS + row) * ND + hf * 32;
    const float* Vbase = g_V + ((size_t)bh * NS + row) * ND + hf * 32;

    for (int kt = 0; kt < 32; kt++) {
        // ---- issue K,V tile copies (GMEM -> SMEM, no registers) ----
        {
            const float* Kg = Kbase + (size_t)kt * 64 * ND;
            const float* Vg = Vbase + (size_t)kt * 64 * ND;
#pragma unroll
            for (int j = 0; j < 8; j++) {
                cpasync16(ks_dst + j * 16, Kg + j * 4);
                cpasync16(vs_dst + j * 16, Vg + j * 4);
            }
            CP_COMMIT();
        }

        // ---- fused threefry dropout, in the cp.async latency shadow ----
        uint32_t klo = 0u, khi = 0u;
        {
            uint32_t e0 = ebl + (uint32_t)kt * 64;
#pragma unroll 2
            for (int nt = 0; nt < 8; nt++) {
                klo |= keep2(e0 + nt * 8) << (2 * nt);
                khi |= keep2(e0 + 8u * NS + nt * 8) << (2 * nt);
            }
        }

        CP_WAIT0();
        __syncthreads();

        // ---- S = Q @ K^T ----
        float s[8][4] = {};
#pragma unroll
        for (int kc = 0; kc < 8; kc++) {
#pragma unroll
            for (int nt = 0; nt < 8; nt++) {
                uint32_t b0 = Ks[(nt * 8 + gi) * 68 + kc * 8 + ci];
                uint32_t b1 = Ks[(nt * 8 + gi) * 68 + kc * 8 + ci + 4];
                mma8(s[nt], qf[kc], b0, b1);
            }
        }

        // ---- mask + online softmax ----
        float mxl = -3.0e38f, mxh = -3.0e38f;
#pragma unroll
        for (int nt = 0; nt < 8; nt++) {
            const float* mrow = mask_lo + kt * 64 + nt * 8 + 2 * ci;
            float2 ml = *reinterpret_cast<const float2*>(mrow);
            float2 mh = *reinterpret_cast<const float2*>(mrow + 8 * NS);
            s[nt][0] += ml.x; s[nt][1] += ml.y;
            s[nt][2] += mh.x; s[nt][3] += mh.y;
            mxl = fmaxf(mxl, fmaxf(s[nt][0], s[nt][1]));
            mxh = fmaxf(mxh, fmaxf(s[nt][2], s[nt][3]));
        }
        mxl = fmaxf(mxl, __shfl_xor_sync(0xffffffffu, mxl, 1));
        mxl = fmaxf(mxl, __shfl_xor_sync(0xffffffffu, mxl, 2));
        mxh = fmaxf(mxh, __shfl_xor_sync(0xffffffffu, mxh, 1));
        mxh = fmaxf(mxh, __shfl_xor_sync(0xffffffffu, mxh, 2));

        float nml = fmaxf(m_lo, mxl), nmh = fmaxf(m_hi, mxh);
        float scl = __expf(m_lo - nml), sch = __expf(m_hi - nmh);
        m_lo = nml; m_hi = nmh;

        float suml = 0.f, sumh = 0.f;
#pragma unroll
        for (int nt = 0; nt < 8; nt++) {
            s[nt][0] = __expf(s[nt][0] - nml);
            s[nt][1] = __expf(s[nt][1] - nml);
            s[nt][2] = __expf(s[nt][2] - nmh);
            s[nt][3] = __expf(s[nt][3] - nmh);
            suml += s[nt][0] + s[nt][1];
            sumh += s[nt][2] + s[nt][3];
        }
        suml += __shfl_xor_sync(0xffffffffu, suml, 1);
        suml += __shfl_xor_sync(0xffffffffu, suml, 2);
        sumh += __shfl_xor_sync(0xffffffffu, sumh, 1);
        sumh += __shfl_xor_sync(0xffffffffu, sumh, 2);
        l_lo = l_lo * scl + suml;
        l_hi = l_hi * sch + sumh;
#pragma unroll
        for (int nt = 0; nt < 8; nt++) {
            oacc[nt][0] *= scl; oacc[nt][1] *= scl;
            oacc[nt][2] *= sch; oacc[nt][3] *= sch;
        }

        // ---- dropout apply + P store (per-warp private region) ----
        uint32_t* Pw = Ps + w * 16 * 68;
#pragma unroll
        for (int nt = 0; nt < 8; nt++) {
            int c0 = nt * 8 + 2 * ci;
            uint2 plo, phi;
            plo.x = ((klo >> (2 * nt)) & 1u)     ? f2tf32(s[nt][0]) : 0u;
            plo.y = ((klo >> (2 * nt + 1)) & 1u) ? f2tf32(s[nt][1]) : 0u;
            phi.x = ((khi >> (2 * nt)) & 1u)     ? f2tf32(s[nt][2]) : 0u;
            phi.y = ((khi >> (2 * nt + 1)) & 1u) ? f2tf32(s[nt][3]) : 0u;
            *reinterpret_cast<uint2*>(Pw + gi * 68 + c0) = plo;
            *reinterpret_cast<uint2*>(Pw + (gi + 8) * 68 + c0) = phi;
        }
        __syncwarp();

        // ---- O += P @ V ----
#pragma unroll
        for (int kc = 0; kc < 8; kc++) {
            uint32_t a[4];
            a[0] = Pw[gi * 68 + kc * 8 + ci];
            a[1] = Pw[(gi + 8) * 68 + kc * 8 + ci];
            a[2] = Pw[gi * 68 + kc * 8 + ci + 4];
            a[3] = Pw[(gi + 8) * 68 + kc * 8 + ci + 4];
#pragma unroll
            for (int nt = 0; nt < 8; nt++) {
                uint32_t b0 = Vs[(kc * 8 + ci) * 72 + nt * 8 + gi];
                uint32_t b1 = Vs[(kc * 8 + ci + 4) * 72 + nt * 8 + gi];
                mma8(oacc[nt], a, b0, b1);
            }
        }
        __syncthreads();
    }

    // epilogue: out = oacc / (l * 0.9)
    float invl = 1.0f / (l_lo * 0.9f);
    float invh = 1.0f / (l_hi * 0.9f);
    float* out_lo = out + ((size_t)bh * NS + rlo) * ND;
#pragma unroll
    for (int nt = 0; nt < 8; nt++) {
        float2 a, c;
        a.x = oacc[nt][0] * invl; a.y = oacc[nt][1] * invl;
        c.x = oacc[nt][2] * invh; c.y = oacc[nt][3] * invh;
        *reinterpret_cast<float2*>(out_lo + nt * 8 + 2 * ci) = a;
        *reinterpret_cast<float2*>(out_lo + 8 * ND + nt * 8 + 2 * ci) = c;
    }
}

// ---------------------------------------------------------------------------
extern "C" void kernel_launch(void* const* d_in, const int* in_sizes, int n_in,
                              void* d_out, int out_size) {
    (void)in_sizes; (void)n_in; (void)out_size;
    const float* q   = (const float*)d_in[0];
    const float* k   = (const float*)d_in[1];
    const float* v   = (const float*)d_in[2];
    const float* msk = (const float*)d_in[3];
    const float* Wq  = (const float*)d_in[4];
    const float* bq  = (const float*)d_in[5];
    const float* Wk  = (const float*)d_in[6];
    const float* bk  = (const float*)d_in[7];
    const float* Wv  = (const float*)d_in[8];
    const float* bv  = (const float*)d_in[9];
    float* out = (float*)d_out;

    const int smem_bytes = SMEM_WORDS * 4;   // 53248 B
    cudaFuncSetAttribute(attn_mma_kernel,
                         cudaFuncAttributeMaxDynamicSharedMemorySize, smem_bytes);

    dim3 pgrid(1024, 3);
    proj_kernel<<<pgrid, 256>>>(q, k, v, Wq, Wk, Wv, bq, bk, bv);

    dim3 grid(NS / 64, NH, NB);
    attn_mma_kernel<<<grid, 128, smem_bytes>>>(msk, out);
}

// round 12
// speedup vs baseline: 1.3570x; 1.3570x over previous
#include <cuda_runtime.h>
#include <cstdint>

#define NB 2
#define NH 16
#define NS 2048
#define ND 64

// Scratch (allocation-free rule: __device__ globals)
// g_Q/g_K/g_V hold tf32-rounded bit patterns (Q pre-scaled by 1/8),
// produced by proj_kernel, consumed raw by attn (bit-identical to R5 math).
__device__ float g_Q[NB*NH*NS*ND];
__device__ float g_K[NB*NH*NS*ND];
__device__ float g_V[NB*NH*NS*ND];

// ---------------------------------------------------------------------------
// helpers
// ---------------------------------------------------------------------------
__device__ __forceinline__ uint32_t f2tf32(float x) {
    uint32_t r;
    asm("cvt.rna.tf32.f32 %0, %1;" : "=r"(r) : "f"(x));
    return r;
}
// m16n8k8 tf32 warp MMA, fp32 accumulate (base ISA, works on sm_103 target)
__device__ __forceinline__ void mma8(float* c, const uint32_t* a,
                                     uint32_t b0, uint32_t b1) {
    asm volatile(
        "mma.sync.aligned.m16n8k8.row.col.f32.tf32.tf32.f32 "
        "{%0,%1,%2,%3}, {%4,%5,%6,%7}, {%8,%9}, {%0,%1,%2,%3};"
        : "+f"(c[0]), "+f"(c[1]), "+f"(c[2]), "+f"(c[3])
        : "r"(a[0]), "r"(a[1]), "r"(a[2]), "r"(a[3]), "r"(b0), "r"(b1));
}
__device__ __forceinline__ uint32_t smem_u32(const void* p) {
    uint32_t a;
    asm("{ .reg .u64 t; cvta.to.shared.u64 t, %1; cvt.u32.u64 %0, t; }"
        : "=r"(a) : "l"(p));
    return a;
}
__device__ __forceinline__ void cpasync16(uint32_t dst, const void* src) {
    asm volatile("cp.async.cg.shared.global [%0], [%1], 16;"
                 :: "r"(dst), "l"(src));
}
#define CP_COMMIT() asm volatile("cp.async.commit_group;" ::: "memory")
#define CP_WAIT0()  asm volatile("cp.async.wait_group 0;" ::: "memory")

// ---------------------------------------------------------------------------
// JAX partitionable threefry2x32, key=(0,42): bits[i] = o0^o1, counter (0,i)
// keep2: two interleaved ciphers (elements e, e+1).
// In the mainloop, NEXT tile's bits are computed inside the PV-mma loop so
// the PRNG alu stream co-issues with tensor/LDS work instead of phasing.
// ---------------------------------------------------------------------------
__device__ __forceinline__ uint32_t rotl32(uint32_t x, int r) {
    return __funnelshift_l(x, x, r);
}
#define KEEP_THRESH 0xE6666600u   // uniform < 0.9f, exact integer reduction

__device__ __forceinline__ uint32_t keep2(uint32_t e) {
    const uint32_t k0 = 0u, k1 = 42u, k2 = 0u ^ 42u ^ 0x1BD11BDAu;
    uint32_t a0 = k0, b0 = e + k1;
    uint32_t a1 = k0, b1 = e + 1u + k1;
#define TF_R2(r) { a0 += b0; b0 = rotl32(b0, (r)) ^ a0;                        \
                   a1 += b1; b1 = rotl32(b1, (r)) ^ a1; }
    TF_R2(13) TF_R2(15) TF_R2(26) TF_R2(6)
    a0 += k1; a1 += k1; b0 += k2 + 1u; b1 += k2 + 1u;
    TF_R2(17) TF_R2(29) TF_R2(16) TF_R2(24)
    a0 += k2; a1 += k2; b0 += k0 + 2u; b1 += k0 + 2u;
    TF_R2(13) TF_R2(15) TF_R2(26) TF_R2(6)
    a0 += k0; a1 += k0; b0 += k1 + 3u; b1 += k1 + 3u;
    TF_R2(17) TF_R2(29) TF_R2(16) TF_R2(24)
    a0 += k1; a1 += k1; b0 += k2 + 4u; b1 += k2 + 4u;
    TF_R2(13) TF_R2(15) TF_R2(26) TF_R2(6)
    a0 += k2; a1 += k2; b0 += k0 + 5u; b1 += k0 + 5u;
#undef TF_R2
    uint32_t r = ((a0 ^ b0) < KEEP_THRESH) ? 1u : 0u;
    r |= ((a1 ^ b1) < KEEP_THRESH) ? 2u : 0u;
    return r;
}

// ---------------------------------------------------------------------------
// QKV projection: Y = tf32_rna(X @ W^T + b), Q additionally scaled by 1/8.
// Output [B,H,S,D]. One launch, grid.y selects {Q,K,V}.
// ---------------------------------------------------------------------------
__global__ void proj_kernel(const float* __restrict__ Xq,
                            const float* __restrict__ Xk,
                            const float* __restrict__ Xv,
                            const float* __restrict__ Wq_,
                            const float* __restrict__ Wk_,
                            const float* __restrict__ Wv_,
                            const float* __restrict__ bq_,
                            const float* __restrict__ bk_,
                            const float* __restrict__ bv_) {
    __shared__ __align__(16) float Xt[64][68];
    __shared__ __align__(16) float Wt[64][68];
    __shared__ float bs[64];
    int which = blockIdx.y;
    const float* X = (which == 0) ? Xq : (which == 1) ? Xk : Xv;
    const float* W = (which == 0) ? Wq_ : (which == 1) ? Wk_ : Wv_;
    const float* bias = (which == 0) ? bq_ : (which == 1) ? bk_ : bv_;
    float* Y = (which == 0) ? g_Q : (which == 1) ? g_K : g_V;
    float scale = (which == 0) ? 0.125f : 1.0f;

    int tid = threadIdx.x;
    if (tid < 64) bs[tid] = bias[tid];
    int r0 = blockIdx.x * 64;

#pragma unroll
    for (int r = 0; r < 4; r++) {
        int fidx = tid + r * 256;
        int row = fidx >> 4, dg = fidx & 15;
        int pg = (((row >> 2) ^ dg) << 2) + (row & 3);
        float4 w4 = reinterpret_cast<const float4*>(W)[fidx];
        Wt[4*dg+0][pg] = w4.x; Wt[4*dg+1][pg] = w4.y;
        Wt[4*dg+2][pg] = w4.z; Wt[4*dg+3][pg] = w4.w;
        float4 x4 = reinterpret_cast<const float4*>(X + (size_t)(r0 + row) * 64)[dg];
        Xt[4*dg+0][pg] = x4.x; Xt[4*dg+1][pg] = x4.y;
        Xt[4*dg+2][pg] = x4.z; Xt[4*dg+3][pg] = x4.w;
    }
    __syncthreads();

    int ty = tid >> 4, tx = tid & 15;
    float acc[4][4] = {};
#pragma unroll 8
    for (int d = 0; d < 64; d++) {
        int sw = d >> 2;
        float4 xv = *reinterpret_cast<float4*>(&Xt[d][(ty ^ sw) << 2]);
        float4 wv = *reinterpret_cast<float4*>(&Wt[d][(tx ^ sw) << 2]);
        float xa[4] = {xv.x, xv.y, xv.z, xv.w};
        float wa[4] = {wv.x, wv.y, wv.z, wv.w};
#pragma unroll
        for (int i = 0; i < 4; i++)
#pragma unroll
            for (int j = 0; j < 4; j++) acc[i][j] += xa[i] * wa[j];
    }

#pragma unroll
    for (int i = 0; i < 4; i++) {
        int r = r0 + ty * 4 + i;
        int b = r >> 15;
        int rem = r & 32767;
        int s = rem >> 4, h = rem & 15;
        uint4 o;
        o.x = f2tf32((acc[i][0] + bs[tx*4+0]) * scale);
        o.y = f2tf32((acc[i][1] + bs[tx*4+1]) * scale);
        o.z = f2tf32((acc[i][2] + bs[tx*4+2]) * scale);
        o.w = f2tf32((acc[i][3] + bs[tx*4+3]) * scale);
        reinterpret_cast<uint4*>(Y + ((size_t)(b*NH + h)*NS + s)*ND)[tx] = o;
    }
}

// ---------------------------------------------------------------------------
// Warp-MMA (m16n8k8 tf32) flash attention with PIPELINED threefry dropout:
// tile kt+1's keep bits are generated inside tile kt's PV-mma loop so the
// PRNG (pure alu) co-issues with tensor/LDS work. Tile 0's bits are computed
// in the prologue under the Q cp.async latency.
// Block: 64 queries x head x batch, 128 threads = 4 warps, 3 blocks/SM.
// ---------------------------------------------------------------------------
#define KS_OFF 0
#define VS_OFF 4352          /* 64*68 */
#define PS_OFF 8960          /* + 64*72 */
#define SMEM_WORDS 13312     /* + 4*16*68 */

__global__ __launch_bounds__(128, 3) void attn_mma_kernel(
        const float* __restrict__ mask, float* __restrict__ out) {
    extern __shared__ __align__(16) uint32_t sm[];
    uint32_t* Ks = sm + KS_OFF;
    uint32_t* Vs = sm + VS_OFF;
    uint32_t* Ps = sm + PS_OFF;
    uint32_t sb = smem_u32(sm);

    int tid = threadIdx.x;
    int lane = tid & 31, w = tid >> 5;       // 4 warps
    int gi = lane >> 2, ci = lane & 3;
    int qt = blockIdx.x, h = blockIdx.y, b = blockIdx.z;
    int bh = b * NH + h;
    int q0 = qt * 64;

    int row = tid >> 1, hf = tid & 1;        // staging: 64 rows x 2 halves

    // staging smem byte-addresses for this thread
    uint32_t ks_dst = sb + (KS_OFF + row * 68 + hf * 32) * 4;
    uint32_t vs_dst = sb + (VS_OFF + row * 72 + hf * 32) * 4;

    int rlo = q0 + w * 16 + gi;              // rhi = rlo + 8 (derived)
    const float* mask_lo = mask + ((size_t)b * NS + rlo) * NS;
    uint32_t ebl = (uint32_t)(bh * NS + rlo) * NS + 2 * ci;   // hi = +8*NS

    // ---- stage Q tile via cp.async; compute tile-0 keep bits in its shadow
    uint32_t klo = 0u, khi = 0u;
    {
        uint32_t ps_dst = sb + (PS_OFF + row * 68 + hf * 32) * 4;
        const float* Qg = g_Q + ((size_t)bh * NS + q0 + row) * ND + hf * 32;
#pragma unroll
        for (int j = 0; j < 8; j++)
            cpasync16(ps_dst + j * 16, Qg + j * 4);
        CP_COMMIT();
#pragma unroll 2
        for (int nt = 0; nt < 8; nt++) {
            klo |= keep2(ebl + nt * 8) << (2 * nt);
            khi |= keep2(ebl + 8u * NS + nt * 8) << (2 * nt);
        }
        CP_WAIT0();
    }
    __syncthreads();
    uint32_t qf[8][4];
    {
        const uint32_t* Qs = Ps + (w * 16) * 68;
#pragma unroll
        for (int kc = 0; kc < 8; kc++) {
            qf[kc][0] = Qs[gi * 68 + kc * 8 + ci];
            qf[kc][1] = Qs[(gi + 8) * 68 + kc * 8 + ci];
            qf[kc][2] = Qs[gi * 68 + kc * 8 + ci + 4];
            qf[kc][3] = Qs[(gi + 8) * 68 + kc * 8 + ci + 4];
        }
    }
    __syncthreads();   // Ps will be overwritten as P-buffer in the mainloop

    float oacc[8][4] = {};
    float m_lo = -3.0e38f, m_hi = -3.0e38f, l_lo = 0.f, l_hi = 0.f;

    const float* Kbase = g_K + ((size_t)bh * NS + row) * ND + hf * 32;
    const float* Vbase = g_V + ((size_t)bh * NS + row) * ND + hf * 32;

    for (int kt = 0; kt < 32; kt++) {
        // ---- issue K,V tile copies (GMEM -> SMEM, no registers) ----
        {
            const float* Kg = Kbase + (size_t)kt * 64 * ND;
            const float* Vg = Vbase + (size_t)kt * 64 * ND;
#pragma unroll
            for (int j = 0; j < 8; j++) {
                cpasync16(ks_dst + j * 16, Kg + j * 4);
                cpasync16(vs_dst + j * 16, Vg + j * 4);
            }
            CP_COMMIT();
        }
        CP_WAIT0();
        __syncthreads();

        // ---- S = Q @ K^T ----
        float s[8][4] = {};
#pragma unroll
        for (int kc = 0; kc < 8; kc++) {
#pragma unroll
            for (int nt = 0; nt < 8; nt++) {
                uint32_t b0 = Ks[(nt * 8 + gi) * 68 + kc * 8 + ci];
                uint32_t b1 = Ks[(nt * 8 + gi) * 68 + kc * 8 + ci + 4];
                mma8(s[nt], qf[kc], b0, b1);
            }
        }

        // ---- mask + online softmax ----
        float mxl = -3.0e38f, mxh = -3.0e38f;
#pragma unroll
        for (int nt = 0; nt < 8; nt++) {
            const float* mrow = mask_lo + kt * 64 + nt * 8 + 2 * ci;
            float2 ml = *reinterpret_cast<const float2*>(mrow);
            float2 mh = *reinterpret_cast<const float2*>(mrow + 8 * NS);
            s[nt][0] += ml.x; s[nt][1] += ml.y;
            s[nt][2] += mh.x; s[nt][3] += mh.y;
            mxl = fmaxf(mxl, fmaxf(s[nt][0], s[nt][1]));
            mxh = fmaxf(mxh, fmaxf(s[nt][2], s[nt][3]));
        }
        mxl = fmaxf(mxl, __shfl_xor_sync(0xffffffffu, mxl, 1));
        mxl = fmaxf(mxl, __shfl_xor_sync(0xffffffffu, mxl, 2));
        mxh = fmaxf(mxh, __shfl_xor_sync(0xffffffffu, mxh, 1));
        mxh = fmaxf(mxh, __shfl_xor_sync(0xffffffffu, mxh, 2));

        float nml = fmaxf(m_lo, mxl), nmh = fmaxf(m_hi, mxh);
        float scl = __expf(m_lo - nml), sch = __expf(m_hi - nmh);
        m_lo = nml; m_hi = nmh;

        float suml = 0.f, sumh = 0.f;
#pragma unroll
        for (int nt = 0; nt < 8; nt++) {
            s[nt][0] = __expf(s[nt][0] - nml);
            s[nt][1] = __expf(s[nt][1] - nml);
            s[nt][2] = __expf(s[nt][2] - nmh);
            s[nt][3] = __expf(s[nt][3] - nmh);
            suml += s[nt][0] + s[nt][1];
            sumh += s[nt][2] + s[nt][3];
        }
        suml += __shfl_xor_sync(0xffffffffu, suml, 1);
        suml += __shfl_xor_sync(0xffffffffu, suml, 2);
        sumh += __shfl_xor_sync(0xffffffffu, sumh, 1);
        sumh += __shfl_xor_sync(0xffffffffu, sumh, 2);
        l_lo = l_lo * scl + suml;
        l_hi = l_hi * sch + sumh;
#pragma unroll
        for (int nt = 0; nt < 8; nt++) {
            oacc[nt][0] *= scl; oacc[nt][1] *= scl;
            oacc[nt][2] *= sch; oacc[nt][3] *= sch;
        }

        // ---- dropout apply + P store (per-warp private region) ----
        uint32_t* Pw = Ps + w * 16 * 68;
#pragma unroll
        for (int nt = 0; nt < 8; nt++) {
            int c0 = nt * 8 + 2 * ci;
            uint2 plo, phi;
            plo.x = ((klo >> (2 * nt)) & 1u)     ? f2tf32(s[nt][0]) : 0u;
            plo.y = ((klo >> (2 * nt + 1)) & 1u) ? f2tf32(s[nt][1]) : 0u;
            phi.x = ((khi >> (2 * nt)) & 1u)     ? f2tf32(s[nt][2]) : 0u;
            phi.y = ((khi >> (2 * nt + 1)) & 1u) ? f2tf32(s[nt][3]) : 0u;
            *reinterpret_cast<uint2*>(Pw + gi * 68 + c0) = plo;
            *reinterpret_cast<uint2*>(Pw + (gi + 8) * 68 + c0) = phi;
        }
        __syncwarp();

        // ---- O += P @ V, INTERLEAVED with tile kt+1's PRNG ----
        uint32_t e0n = ebl + (uint32_t)(kt + 1) * 64;
        uint32_t nklo = 0u, nkhi = 0u;
#pragma unroll
        for (int kc = 0; kc < 8; kc++) {
            uint32_t a[4];
            a[0] = Pw[gi * 68 + kc * 8 + ci];
            a[1] = Pw[(gi + 8) * 68 + kc * 8 + ci];
            a[2] = Pw[gi * 68 + kc * 8 + ci + 4];
            a[3] = Pw[(gi + 8) * 68 + kc * 8 + ci + 4];
            // next-tile keep bits: independent alu stream, co-issues with mma
            nklo |= keep2(e0n + kc * 8) << (2 * kc);
            nkhi |= keep2(e0n + 8u * NS + kc * 8) << (2 * kc);
#pragma unroll
            for (int nt = 0; nt < 8; nt++) {
                uint32_t b0 = Vs[(kc * 8 + ci) * 72 + nt * 8 + gi];
                uint32_t b1 = Vs[(kc * 8 + ci + 4) * 72 + nt * 8 + gi];
                mma8(oacc[nt], a, b0, b1);
            }
        }
        klo = nklo; khi = nkhi;
        __syncthreads();
    }

    // epilogue: out = oacc / (l * 0.9)
    float invl = 1.0f / (l_lo * 0.9f);
    float invh = 1.0f / (l_hi * 0.9f);
    float* out_lo = out + ((size_t)bh * NS + rlo) * ND;
#pragma unroll
    for (int nt = 0; nt < 8; nt++) {
        float2 a, c;
        a.x = oacc[nt][0] * invl; a.y = oacc[nt][1] * invl;
        c.x = oacc[nt][2] * invh; c.y = oacc[nt][3] * invh;
        *reinterpret_cast<float2*>(out_lo + nt * 8 + 2 * ci) = a;
        *reinterpret_cast<float2*>(out_lo + 8 * ND + nt * 8 + 2 * ci) = c;
    }
}

// ---------------------------------------------------------------------------
extern "C" void kernel_launch(void* const* d_in, const int* in_sizes, int n_in,
                              void* d_out, int out_size) {
    (void)in_sizes; (void)n_in; (void)out_size;
    const float* q   = (const float*)d_in[0];
    const float* k   = (const float*)d_in[1];
    const float* v   = (const float*)d_in[2];
    const float* msk = (const float*)d_in[3];
    const float* Wq  = (const float*)d_in[4];
    const float* bq  = (const float*)d_in[5];
    const float* Wk  = (const float*)d_in[6];
    const float* bk  = (const float*)d_in[7];
    const float* Wv  = (const float*)d_in[8];
    const float* bv  = (const float*)d_in[9];
    float* out = (float*)d_out;

    const int smem_bytes = SMEM_WORDS * 4;   // 53248 B
    cudaFuncSetAttribute(attn_mma_kernel,
                         cudaFuncAttributeMaxDynamicSharedMemorySize, smem_bytes);

    dim3 pgrid(1024, 3);
    proj_kernel<<<pgrid, 256>>>(q, k, v, Wq, Wk, Wv, bq, bk, bv);

    dim3 grid(NS / 64, NH, NB);
    attn_mma_kernel<<<grid, 128, smem_bytes>>>(msk, out);
}

// round 13
// speedup vs baseline: 1.5511x; 1.1430x over previous
#include <cuda_runtime.h>
#include <cstdint>

#define NB 2
#define NH 16
#define NS 2048
#define ND 64

// Scratch (allocation-free rule: __device__ globals)
// g_Q/g_K/g_V hold tf32-rounded bit patterns (Q pre-scaled by 1/8),
// produced by proj_kernel, consumed raw by attn (bit-identical to R5 math).
__device__ float g_Q[NB*NH*NS*ND];
__device__ float g_K[NB*NH*NS*ND];
__device__ float g_V[NB*NH*NS*ND];

// ---------------------------------------------------------------------------
// helpers
// ---------------------------------------------------------------------------
__device__ __forceinline__ uint32_t f2tf32(float x) {
    uint32_t r;
    asm("cvt.rna.tf32.f32 %0, %1;" : "=r"(r) : "f"(x));
    return r;
}
// m16n8k8 tf32 warp MMA, fp32 accumulate (base ISA, works on sm_103 target)
__device__ __forceinline__ void mma8(float* c, const uint32_t* a,
                                     uint32_t b0, uint32_t b1) {
    asm volatile(
        "mma.sync.aligned.m16n8k8.row.col.f32.tf32.tf32.f32 "
        "{%0,%1,%2,%3}, {%4,%5,%6,%7}, {%8,%9}, {%0,%1,%2,%3};"
        : "+f"(c[0]), "+f"(c[1]), "+f"(c[2]), "+f"(c[3])
        : "r"(a[0]), "r"(a[1]), "r"(a[2]), "r"(a[3]), "r"(b0), "r"(b1));
}
__device__ __forceinline__ uint32_t smem_u32(const void* p) {
    uint32_t a;
    asm("{ .reg .u64 t; cvta.to.shared.u64 t, %1; cvt.u32.u64 %0, t; }"
        : "=r"(a) : "l"(p));
    return a;
}
__device__ __forceinline__ void cpasync16(uint32_t dst, const void* src) {
    asm volatile("cp.async.cg.shared.global [%0], [%1], 16;"
                 :: "r"(dst), "l"(src));
}
#define CP_COMMIT() asm volatile("cp.async.commit_group;" ::: "memory")
#define CP_WAIT0()  asm volatile("cp.async.wait_group 0;" ::: "memory")

// ---------------------------------------------------------------------------
// JAX partitionable threefry2x32, key=(0,42): bits[i] = o0^o1, counter (0,i)
// R5/R10 form (best measured). Executed between cp.async issue and wait so
// the ALU work hides the GMEM->SMEM latency of K, V, AND mask tiles.
// ---------------------------------------------------------------------------
__device__ __forceinline__ uint32_t rotl32(uint32_t x, int r) {
    return __funnelshift_l(x, x, r);
}
#define KEEP_THRESH 0xE6666600u   // uniform < 0.9f, exact integer reduction

// returns bit0 = keep(e), bit1 = keep(e+1); two interleaved ciphers for ILP
__device__ __forceinline__ uint32_t keep2(uint32_t e) {
    const uint32_t k0 = 0u, k1 = 42u, k2 = 0u ^ 42u ^ 0x1BD11BDAu;
    uint32_t a0 = k0, b0 = e + k1;
    uint32_t a1 = k0, b1 = e + 1u + k1;
#define TF_R2(r) { a0 += b0; b0 = rotl32(b0, (r)) ^ a0;                        \
                   a1 += b1; b1 = rotl32(b1, (r)) ^ a1; }
    TF_R2(13) TF_R2(15) TF_R2(26) TF_R2(6)
    a0 += k1; a1 += k1; b0 += k2 + 1u; b1 += k2 + 1u;
    TF_R2(17) TF_R2(29) TF_R2(16) TF_R2(24)
    a0 += k2; a1 += k2; b0 += k0 + 2u; b1 += k0 + 2u;
    TF_R2(13) TF_R2(15) TF_R2(26) TF_R2(6)
    a0 += k0; a1 += k0; b0 += k1 + 3u; b1 += k1 + 3u;
    TF_R2(17) TF_R2(29) TF_R2(16) TF_R2(24)
    a0 += k1; a1 += k1; b0 += k2 + 4u; b1 += k2 + 4u;
    TF_R2(13) TF_R2(15) TF_R2(26) TF_R2(6)
    a0 += k2; a1 += k2; b0 += k0 + 5u; b1 += k0 + 5u;
#undef TF_R2
    uint32_t r = ((a0 ^ b0) < KEEP_THRESH) ? 1u : 0u;
    r |= ((a1 ^ b1) < KEEP_THRESH) ? 2u : 0u;
    return r;
}

// ---------------------------------------------------------------------------
// QKV projection: Y = tf32_rna(X @ W^T + b), Q additionally scaled by 1/8.
// Output [B,H,S,D]. One launch, grid.y selects {Q,K,V}.
// ---------------------------------------------------------------------------
__global__ void proj_kernel(const float* __restrict__ Xq,
                            const float* __restrict__ Xk,
                            const float* __restrict__ Xv,
                            const float* __restrict__ Wq_,
                            const float* __restrict__ Wk_,
                            const float* __restrict__ Wv_,
                            const float* __restrict__ bq_,
                            const float* __restrict__ bk_,
                            const float* __restrict__ bv_) {
    __shared__ __align__(16) float Xt[64][68];
    __shared__ __align__(16) float Wt[64][68];
    __shared__ float bs[64];
    int which = blockIdx.y;
    const float* X = (which == 0) ? Xq : (which == 1) ? Xk : Xv;
    const float* W = (which == 0) ? Wq_ : (which == 1) ? Wk_ : Wv_;
    const float* bias = (which == 0) ? bq_ : (which == 1) ? bk_ : bv_;
    float* Y = (which == 0) ? g_Q : (which == 1) ? g_K : g_V;
    float scale = (which == 0) ? 0.125f : 1.0f;

    int tid = threadIdx.x;
    if (tid < 64) bs[tid] = bias[tid];
    int r0 = blockIdx.x * 64;

#pragma unroll
    for (int r = 0; r < 4; r++) {
        int fidx = tid + r * 256;
        int row = fidx >> 4, dg = fidx & 15;
        int pg = (((row >> 2) ^ dg) << 2) + (row & 3);
        float4 w4 = reinterpret_cast<const float4*>(W)[fidx];
        Wt[4*dg+0][pg] = w4.x; Wt[4*dg+1][pg] = w4.y;
        Wt[4*dg+2][pg] = w4.z; Wt[4*dg+3][pg] = w4.w;
        float4 x4 = reinterpret_cast<const float4*>(X + (size_t)(r0 + row) * 64)[dg];
        Xt[4*dg+0][pg] = x4.x; Xt[4*dg+1][pg] = x4.y;
        Xt[4*dg+2][pg] = x4.z; Xt[4*dg+3][pg] = x4.w;
    }
    __syncthreads();

    int ty = tid >> 4, tx = tid & 15;
    float acc[4][4] = {};
#pragma unroll 8
    for (int d = 0; d < 64; d++) {
        int sw = d >> 2;
        float4 xv = *reinterpret_cast<float4*>(&Xt[d][(ty ^ sw) << 2]);
        float4 wv = *reinterpret_cast<float4*>(&Wt[d][(tx ^ sw) << 2]);
        float xa[4] = {xv.x, xv.y, xv.z, xv.w};
        float wa[4] = {wv.x, wv.y, wv.z, wv.w};
#pragma unroll
        for (int i = 0; i < 4; i++)
#pragma unroll
            for (int j = 0; j < 4; j++) acc[i][j] += xa[i] * wa[j];
    }

#pragma unroll
    for (int i = 0; i < 4; i++) {
        int r = r0 + ty * 4 + i;
        int b = r >> 15;
        int rem = r & 32767;
        int s = rem >> 4, h = rem & 15;
        uint4 o;
        o.x = f2tf32((acc[i][0] + bs[tx*4+0]) * scale);
        o.y = f2tf32((acc[i][1] + bs[tx*4+1]) * scale);
        o.z = f2tf32((acc[i][2] + bs[tx*4+2]) * scale);
        o.w = f2tf32((acc[i][3] + bs[tx*4+3]) * scale);
        reinterpret_cast<uint4*>(Y + ((size_t)(b*NH + h)*NS + s)*ND)[tx] = o;
    }
}

// ---------------------------------------------------------------------------
// Warp-MMA (m16n8k8 tf32) flash attention with FUSED threefry dropout.
// R10 structure (best: 752us) + mask tile staged via cp.async into smem:
// the mask LDGs were the last uncovered-latency loads (consumed 2 instrs
// after issue inside softmax); now they ride the same PRNG latency shadow
// as K/V, and softmax reads bank-clean smem (pad-72).
// Block: 64 queries x head x batch, 128 threads = 4 warps, 3 blocks/SM.
// SMEM (uint32): Ks [64][68], Vs [64][72], Ps [4][16][68], Ms [64][72].
// ---------------------------------------------------------------------------
#define KS_OFF 0
#define VS_OFF 4352          /* 64*68 */
#define PS_OFF 8960          /* + 64*72 */
#define MS_OFF 13312         /* + 4*16*68 */
#define SMEM_WORDS 17920     /* + 64*72  -> 71680 B */

__global__ __launch_bounds__(128, 3) void attn_mma_kernel(
        const float* __restrict__ mask, float* __restrict__ out) {
    extern __shared__ __align__(16) uint32_t sm[];
    uint32_t* Ks = sm + KS_OFF;
    uint32_t* Vs = sm + VS_OFF;
    uint32_t* Ps = sm + PS_OFF;
    float*    Ms = reinterpret_cast<float*>(sm + MS_OFF);
    uint32_t sb = smem_u32(sm);

    int tid = threadIdx.x;
    int lane = tid & 31, w = tid >> 5;       // 4 warps
    int gi = lane >> 2, ci = lane & 3;
    int qt = blockIdx.x, h = blockIdx.y, b = blockIdx.z;
    int bh = b * NH + h;
    int q0 = qt * 64;

    int row = tid >> 1, hf = tid & 1;        // staging: 64 rows x 2 halves

    // staging smem byte-addresses for this thread
    uint32_t ks_dst = sb + (KS_OFF + row * 68 + hf * 32) * 4;
    uint32_t vs_dst = sb + (VS_OFF + row * 72 + hf * 32) * 4;
    uint32_t ms_dst = sb + (MS_OFF + row * 72 + hf * 32) * 4;

    // ---- stage Q tile (already tf32+scaled) into Ps via cp.async ----
    {
        uint32_t ps_dst = sb + (PS_OFF + row * 68 + hf * 32) * 4;
        const float* Qg = g_Q + ((size_t)bh * NS + q0 + row) * ND + hf * 32;
#pragma unroll
        for (int j = 0; j < 8; j++)
            cpasync16(ps_dst + j * 16, Qg + j * 4);
        CP_COMMIT();
        CP_WAIT0();
    }
    __syncthreads();
    uint32_t qf[8][4];
    {
        const uint32_t* Qs = Ps + (w * 16) * 68;
#pragma unroll
        for (int kc = 0; kc < 8; kc++) {
            qf[kc][0] = Qs[gi * 68 + kc * 8 + ci];
            qf[kc][1] = Qs[(gi + 8) * 68 + kc * 8 + ci];
            qf[kc][2] = Qs[gi * 68 + kc * 8 + ci + 4];
            qf[kc][3] = Qs[(gi + 8) * 68 + kc * 8 + ci + 4];
        }
    }
    __syncthreads();   // Ps will be overwritten as P-buffer in the mainloop

    float oacc[8][4] = {};
    float m_lo = -3.0e38f, m_hi = -3.0e38f, l_lo = 0.f, l_hi = 0.f;

    int rlo = q0 + w * 16 + gi;              // rhi = rlo + 8 (derived)
    // flat dropout-element base (hi base = lo + 8*NS, constant)
    uint32_t ebl = (uint32_t)(bh * NS + rlo) * NS + 2 * ci;

    const float* Kbase = g_K + ((size_t)bh * NS + row) * ND + hf * 32;
    const float* Vbase = g_V + ((size_t)bh * NS + row) * ND + hf * 32;
    // mask GMEM row for this thread's staging row (row = q-in-block)
    const float* Mbase = mask + ((size_t)b * NS + q0 + row) * NS + hf * 32;

    for (int kt = 0; kt < 32; kt++) {
        // ---- issue K,V,mask tile copies (GMEM -> SMEM, no registers) ----
        {
            const float* Kg = Kbase + (size_t)kt * 64 * ND;
            const float* Vg = Vbase + (size_t)kt * 64 * ND;
            const float* Mg = Mbase + kt * 64;
#pragma unroll
            for (int j = 0; j < 8; j++) {
                cpasync16(ks_dst + j * 16, Kg + j * 4);
                cpasync16(vs_dst + j * 16, Vg + j * 4);
                cpasync16(ms_dst + j * 16, Mg + j * 4);
            }
            CP_COMMIT();
        }

        // ---- fused threefry dropout, in the cp.async latency shadow ----
        uint32_t klo = 0u, khi = 0u;
        {
            uint32_t e0 = ebl + (uint32_t)kt * 64;
#pragma unroll 2
            for (int nt = 0; nt < 8; nt++) {
                klo |= keep2(e0 + nt * 8) << (2 * nt);
                khi |= keep2(e0 + 8u * NS + nt * 8) << (2 * nt);
            }
        }

        CP_WAIT0();
        __syncthreads();

        // ---- S = Q @ K^T ----
        float s[8][4] = {};
#pragma unroll
        for (int kc = 0; kc < 8; kc++) {
#pragma unroll
            for (int nt = 0; nt < 8; nt++) {
                uint32_t b0 = Ks[(nt * 8 + gi) * 68 + kc * 8 + ci];
                uint32_t b1 = Ks[(nt * 8 + gi) * 68 + kc * 8 + ci + 4];
                mma8(s[nt], qf[kc], b0, b1);
            }
        }

        // ---- mask (from smem) + online softmax ----
        const float* Mrow = Ms + (w * 16 + gi) * 72 + 2 * ci;
        float mxl = -3.0e38f, mxh = -3.0e38f;
#pragma unroll
        for (int nt = 0; nt < 8; nt++) {
            float2 ml = *reinterpret_cast<const float2*>(Mrow + nt * 8);
            float2 mh = *reinterpret_cast<const float2*>(Mrow + 8 * 72 + nt * 8);
            s[nt][0] += ml.x; s[nt][1] += ml.y;
            s[nt][2] += mh.x; s[nt][3] += mh.y;
            mxl = fmaxf(mxl, fmaxf(s[nt][0], s[nt][1]));
            mxh = fmaxf(mxh, fmaxf(s[nt][2], s[nt][3]));
        }
        mxl = fmaxf(mxl, __shfl_xor_sync(0xffffffffu, mxl, 1));
        mxl = fmaxf(mxl, __shfl_xor_sync(0xffffffffu, mxl, 2));
        mxh = fmaxf(mxh, __shfl_xor_sync(0xffffffffu, mxh, 1));
        mxh = fmaxf(mxh, __shfl_xor_sync(0xffffffffu, mxh, 2));

        float nml = fmaxf(m_lo, mxl), nmh = fmaxf(m_hi, mxh);
        float scl = __expf(m_lo - nml), sch = __expf(m_hi - nmh);
        m_lo = nml; m_hi = nmh;

        float suml = 0.f, sumh = 0.f;
#pragma unroll
        for (int nt = 0; nt < 8; nt++) {
            s[nt][0] = __expf(s[nt][0] - nml);
            s[nt][1] = __expf(s[nt][1] - nml);
            s[nt][2] = __expf(s[nt][2] - nmh);
            s[nt][3] = __expf(s[nt][3] - nmh);
            suml += s[nt][0] + s[nt][1];
            sumh += s[nt][2] + s[nt][3];
        }
        suml += __shfl_xor_sync(0xffffffffu, suml, 1);
        suml += __shfl_xor_sync(0xffffffffu, suml, 2);
        sumh += __shfl_xor_sync(0xffffffffu, sumh, 1);
        sumh += __shfl_xor_sync(0xffffffffu, sumh, 2);
        l_lo = l_lo * scl + suml;
        l_hi = l_hi * sch + sumh;
#pragma unroll
        for (int nt = 0; nt < 8; nt++) {
            oacc[nt][0] *= scl; oacc[nt][1] *= scl;
            oacc[nt][2] *= sch; oacc[nt][3] *= sch;
        }

        // ---- dropout apply + P store (per-warp private region) ----
        uint32_t* Pw = Ps + w * 16 * 68;
#pragma unroll
        for (int nt = 0; nt < 8; nt++) {
            int c0 = nt * 8 + 2 * ci;
            uint2 plo, phi;
            plo.x = ((klo >> (2 * nt)) & 1u)     ? f2tf32(s[nt][0]) : 0u;
            plo.y = ((klo >> (2 * nt + 1)) & 1u) ? f2tf32(s[nt][1]) : 0u;
            phi.x = ((khi >> (2 * nt)) & 1u)     ? f2tf32(s[nt][2]) : 0u;
            phi.y = ((khi >> (2 * nt + 1)) & 1u) ? f2tf32(s[nt][3]) : 0u;
            *reinterpret_cast<uint2*>(Pw + gi * 68 + c0) = plo;
            *reinterpret_cast<uint2*>(Pw + (gi + 8) * 68 + c0) = phi;
        }
        __syncwarp();

        // ---- O += P @ V ----
#pragma unroll
        for (int kc = 0; kc < 8; kc++) {
            uint32_t a[4];
            a[0] = Pw[gi * 68 + kc * 8 + ci];
            a[1] = Pw[(gi + 8) * 68 + kc * 8 + ci];
            a[2] = Pw[gi * 68 + kc * 8 + ci + 4];
            a[3] = Pw[(gi + 8) * 68 + kc * 8 + ci + 4];
#pragma unroll
            for (int nt = 0; nt < 8; nt++) {
                uint32_t b0 = Vs[(kc * 8 + ci) * 72 + nt * 8 + gi];
                uint32_t b1 = Vs[(kc * 8 + ci + 4) * 72 + nt * 8 + gi];
                mma8(oacc[nt], a, b0, b1);
            }
        }
        __syncthreads();
    }

    // epilogue: out = oacc / (l * 0.9)
    float invl = 1.0f / (l_lo * 0.9f);
    float invh = 1.0f / (l_hi * 0.9f);
    float* out_lo = out + ((size_t)bh * NS + rlo) * ND;
#pragma unroll
    for (int nt = 0; nt < 8; nt++) {
        float2 a, c;
        a.x = oacc[nt][0] * invl; a.y = oacc[nt][1] * invl;
        c.x = oacc[nt][2] * invh; c.y = oacc[nt][3] * invh;
        *reinterpret_cast<float2*>(out_lo + nt * 8 + 2 * ci) = a;
        *reinterpret_cast<float2*>(out_lo + 8 * ND + nt * 8 + 2 * ci) = c;
    }
}

// ---------------------------------------------------------------------------
extern "C" void kernel_launch(void* const* d_in, const int* in_sizes, int n_in,
                              void* d_out, int out_size) {
    (void)in_sizes; (void)n_in; (void)out_size;
    const float* q   = (const float*)d_in[0];
    const float* k   = (const float*)d_in[1];
    const float* v   = (const float*)d_in[2];
    const float* msk = (const float*)d_in[3];
    const float* Wq  = (const float*)d_in[4];
    const float* bq  = (const float*)d_in[5];
    const float* Wk  = (const float*)d_in[6];
    const float* bk  = (const float*)d_in[7];
    const float* Wv  = (const float*)d_in[8];
    const float* bv  = (const float*)d_in[9];
    float* out = (float*)d_out;

    const int smem_bytes = SMEM_WORDS * 4;   // 71680 B
    cudaFuncSetAttribute(attn_mma_kernel,
                         cudaFuncAttributeMaxDynamicSharedMemorySize, smem_bytes);

    dim3 pgrid(1024, 3);
    proj_kernel<<<pgrid, 256>>>(q, k, v, Wq, Wk, Wv, bq, bk, bv);

    dim3 grid(NS / 64, NH, NB);
    attn_mma_kernel<<<grid, 128, smem_bytes>>>(msk, out);
}

// round 14
// speedup vs baseline: 1.7260x; 1.1127x over previous
#include <cuda_runtime.h>
#include <cstdint>

#define NB 2
#define NH 16
#define NS 2048
#define ND 64

// Scratch (allocation-free rule: __device__ globals)
// g_Q/g_K/g_V hold tf32-rounded bit patterns (Q pre-scaled by 1/8),
// produced by proj_kernel, consumed raw by attn (bit-identical to R5 math).
__device__ float g_Q[NB*NH*NS*ND];
__device__ float g_K[NB*NH*NS*ND];
__device__ float g_V[NB*NH*NS*ND];
// split-K partials: unnormalized A, row max m, row denom l, per half
__device__ float g_pA[2][NB*NH][NS][ND];   // 32 MB
__device__ float g_pm[2][NB*NH][NS];
__device__ float g_pl[2][NB*NH][NS];

// ---------------------------------------------------------------------------
// helpers
// ---------------------------------------------------------------------------
__device__ __forceinline__ uint32_t f2tf32(float x) {
    uint32_t r;
    asm("cvt.rna.tf32.f32 %0, %1;" : "=r"(r) : "f"(x));
    return r;
}
// m16n8k8 tf32 warp MMA, fp32 accumulate (base ISA, works on sm_103 target)
__device__ __forceinline__ void mma8(float* c, const uint32_t* a,
                                     uint32_t b0, uint32_t b1) {
    asm volatile(
        "mma.sync.aligned.m16n8k8.row.col.f32.tf32.tf32.f32 "
        "{%0,%1,%2,%3}, {%4,%5,%6,%7}, {%8,%9}, {%0,%1,%2,%3};"
        : "+f"(c[0]), "+f"(c[1]), "+f"(c[2]), "+f"(c[3])
        : "r"(a[0]), "r"(a[1]), "r"(a[2]), "r"(a[3]), "r"(b0), "r"(b1));
}
__device__ __forceinline__ uint32_t smem_u32(const void* p) {
    uint32_t a;
    asm("{ .reg .u64 t; cvta.to.shared.u64 t, %1; cvt.u32.u64 %0, t; }"
        : "=r"(a) : "l"(p));
    return a;
}
__device__ __forceinline__ void cpasync16(uint32_t dst, const void* src) {
    asm volatile("cp.async.cg.shared.global [%0], [%1], 16;"
                 :: "r"(dst), "l"(src));
}
#define CP_COMMIT() asm volatile("cp.async.commit_group;" ::: "memory")
#define CP_WAIT0()  asm volatile("cp.async.wait_group 0;" ::: "memory")

// ---------------------------------------------------------------------------
// JAX partitionable threefry2x32, key=(0,42): bits[i] = o0^o1, counter (0,i)
// R5/R10 form (best measured). Executed between cp.async issue and wait so
// the ALU work hides the K/V GMEM->SMEM latency.
// ---------------------------------------------------------------------------
__device__ __forceinline__ uint32_t rotl32(uint32_t x, int r) {
    return __funnelshift_l(x, x, r);
}
#define KEEP_THRESH 0xE6666600u   // uniform < 0.9f, exact integer reduction

// returns bit0 = keep(e), bit1 = keep(e+1); two interleaved ciphers for ILP
__device__ __forceinline__ uint32_t keep2(uint32_t e) {
    const uint32_t k0 = 0u, k1 = 42u, k2 = 0u ^ 42u ^ 0x1BD11BDAu;
    uint32_t a0 = k0, b0 = e + k1;
    uint32_t a1 = k0, b1 = e + 1u + k1;
#define TF_R2(r) { a0 += b0; b0 = rotl32(b0, (r)) ^ a0;                        \
                   a1 += b1; b1 = rotl32(b1, (r)) ^ a1; }
    TF_R2(13) TF_R2(15) TF_R2(26) TF_R2(6)
    a0 += k1; a1 += k1; b0 += k2 + 1u; b1 += k2 + 1u;
    TF_R2(17) TF_R2(29) TF_R2(16) TF_R2(24)
    a0 += k2; a1 += k2; b0 += k0 + 2u; b1 += k0 + 2u;
    TF_R2(13) TF_R2(15) TF_R2(26) TF_R2(6)
    a0 += k0; a1 += k0; b0 += k1 + 3u; b1 += k1 + 3u;
    TF_R2(17) TF_R2(29) TF_R2(16) TF_R2(24)
    a0 += k1; a1 += k1; b0 += k2 + 4u; b1 += k2 + 4u;
    TF_R2(13) TF_R2(15) TF_R2(26) TF_R2(6)
    a0 += k2; a1 += k2; b0 += k0 + 5u; b1 += k0 + 5u;
#undef TF_R2
    uint32_t r = ((a0 ^ b0) < KEEP_THRESH) ? 1u : 0u;
    r |= ((a1 ^ b1) < KEEP_THRESH) ? 2u : 0u;
    return r;
}

// ---------------------------------------------------------------------------
// QKV projection: Y = tf32_rna(X @ W^T + b), Q additionally scaled by 1/8.
// Output [B,H,S,D]. One launch, grid.y selects {Q,K,V}.
// ---------------------------------------------------------------------------
__global__ void proj_kernel(const float* __restrict__ Xq,
                            const float* __restrict__ Xk,
                            const float* __restrict__ Xv,
                            const float* __restrict__ Wq_,
                            const float* __restrict__ Wk_,
                            const float* __restrict__ Wv_,
                            const float* __restrict__ bq_,
                            const float* __restrict__ bk_,
                            const float* __restrict__ bv_) {
    __shared__ __align__(16) float Xt[64][68];
    __shared__ __align__(16) float Wt[64][68];
    __shared__ float bs[64];
    int which = blockIdx.y;
    const float* X = (which == 0) ? Xq : (which == 1) ? Xk : Xv;
    const float* W = (which == 0) ? Wq_ : (which == 1) ? Wk_ : Wv_;
    const float* bias = (which == 0) ? bq_ : (which == 1) ? bk_ : bv_;
    float* Y = (which == 0) ? g_Q : (which == 1) ? g_K : g_V;
    float scale = (which == 0) ? 0.125f : 1.0f;

    int tid = threadIdx.x;
    if (tid < 64) bs[tid] = bias[tid];
    int r0 = blockIdx.x * 64;

#pragma unroll
    for (int r = 0; r < 4; r++) {
        int fidx = tid + r * 256;
        int row = fidx >> 4, dg = fidx & 15;
        int pg = (((row >> 2) ^ dg) << 2) + (row & 3);
        float4 w4 = reinterpret_cast<const float4*>(W)[fidx];
        Wt[4*dg+0][pg] = w4.x; Wt[4*dg+1][pg] = w4.y;
        Wt[4*dg+2][pg] = w4.z; Wt[4*dg+3][pg] = w4.w;
        float4 x4 = reinterpret_cast<const float4*>(X + (size_t)(r0 + row) * 64)[dg];
        Xt[4*dg+0][pg] = x4.x; Xt[4*dg+1][pg] = x4.y;
        Xt[4*dg+2][pg] = x4.z; Xt[4*dg+3][pg] = x4.w;
    }
    __syncthreads();

    int ty = tid >> 4, tx = tid & 15;
    float acc[4][4] = {};
#pragma unroll 8
    for (int d = 0; d < 64; d++) {
        int sw = d >> 2;
        float4 xv = *reinterpret_cast<float4*>(&Xt[d][(ty ^ sw) << 2]);
        float4 wv = *reinterpret_cast<float4*>(&Wt[d][(tx ^ sw) << 2]);
        float xa[4] = {xv.x, xv.y, xv.z, xv.w};
        float wa[4] = {wv.x, wv.y, wv.z, wv.w};
#pragma unroll
        for (int i = 0; i < 4; i++)
#pragma unroll
            for (int j = 0; j < 4; j++) acc[i][j] += xa[i] * wa[j];
    }

#pragma unroll
    for (int i = 0; i < 4; i++) {
        int r = r0 + ty * 4 + i;
        int b = r >> 15;
        int rem = r & 32767;
        int s = rem >> 4, h = rem & 15;
        uint4 o;
        o.x = f2tf32((acc[i][0] + bs[tx*4+0]) * scale);
        o.y = f2tf32((acc[i][1] + bs[tx*4+1]) * scale);
        o.z = f2tf32((acc[i][2] + bs[tx*4+2]) * scale);
        o.w = f2tf32((acc[i][3] + bs[tx*4+3]) * scale);
        reinterpret_cast<uint4*>(Y + ((size_t)(b*NH + h)*NS + s)*ND)[tx] = o;
    }
}

// ---------------------------------------------------------------------------
// Warp-MMA (m16n8k8 tf32) flash attention with FUSED threefry dropout.
// R10 body (best: 752us) with SPLIT-K: each block handles 16 of 32 k-tiles
// (grid.x = qt*2 + half), writing unnormalized partials (A, m, l); a merge
// kernel combines the two halves. Halves the CTA scheduling quantum: wave
// structure 1024/444=2.31 rounds (tail at 1 block/SM) -> 2048 blocks, tail
// round at 2 blocks/SM.
// Block: 64 queries x half x head x batch, 128 threads, 3 blocks/SM.
// SMEM (uint32): Ks [64][68], Vs [64][72], Ps [4][16][68].
// ---------------------------------------------------------------------------
#define KS_OFF 0
#define VS_OFF 4352          /* 64*68 */
#define PS_OFF 8960          /* + 64*72 */
#define SMEM_WORDS 13312     /* + 4*16*68 */

__global__ __launch_bounds__(128, 3) void attn_mma_kernel(
        const float* __restrict__ mask) {
    extern __shared__ __align__(16) uint32_t sm[];
    uint32_t* Ks = sm + KS_OFF;
    uint32_t* Vs = sm + VS_OFF;
    uint32_t* Ps = sm + PS_OFF;
    uint32_t sb = smem_u32(sm);

    int tid = threadIdx.x;
    int lane = tid & 31, w = tid >> 5;       // 4 warps
    int gi = lane >> 2, ci = lane & 3;
    int qt = blockIdx.x >> 1, half = blockIdx.x & 1;
    int h = blockIdx.y, b = blockIdx.z;
    int bh = b * NH + h;
    int q0 = qt * 64;
    int kt0 = half * 16, kt1 = kt0 + 16;

    int row = tid >> 1, hf = tid & 1;        // staging: 64 rows x 2 halves

    // staging smem byte-addresses for this thread
    uint32_t ks_dst = sb + (KS_OFF + row * 68 + hf * 32) * 4;
    uint32_t vs_dst = sb + (VS_OFF + row * 72 + hf * 32) * 4;

    // ---- stage Q tile (already tf32+scaled) into Ps via cp.async ----
    {
        uint32_t ps_dst = sb + (PS_OFF + row * 68 + hf * 32) * 4;
        const float* Qg = g_Q + ((size_t)bh * NS + q0 + row) * ND + hf * 32;
#pragma unroll
        for (int j = 0; j < 8; j++)
            cpasync16(ps_dst + j * 16, Qg + j * 4);
        CP_COMMIT();
        CP_WAIT0();
    }
    __syncthreads();
    uint32_t qf[8][4];
    {
        const uint32_t* Qs = Ps + (w * 16) * 68;
#pragma unroll
        for (int kc = 0; kc < 8; kc++) {
            qf[kc][0] = Qs[gi * 68 + kc * 8 + ci];
            qf[kc][1] = Qs[(gi + 8) * 68 + kc * 8 + ci];
            qf[kc][2] = Qs[gi * 68 + kc * 8 + ci + 4];
            qf[kc][3] = Qs[(gi + 8) * 68 + kc * 8 + ci + 4];
        }
    }
    __syncthreads();   // Ps will be overwritten as P-buffer in the mainloop

    float oacc[8][4] = {};
    float m_lo = -3.0e38f, m_hi = -3.0e38f, l_lo = 0.f, l_hi = 0.f;

    int rlo = q0 + w * 16 + gi;              // rhi = rlo + 8 (derived)
    const float* mask_lo = mask + ((size_t)b * NS + rlo) * NS;
    // flat dropout-element base (hi base = lo + 8*NS, constant)
    uint32_t ebl = (uint32_t)(bh * NS + rlo) * NS + 2 * ci;

    const float* Kbase = g_K + ((size_t)bh * NS + row) * ND + hf * 32;
    const float* Vbase = g_V + ((size_t)bh * NS + row) * ND + hf * 32;

    for (int kt = kt0; kt < kt1; kt++) {
        // ---- issue K,V tile copies (GMEM -> SMEM, no registers) ----
        {
            const float* Kg = Kbase + (size_t)kt * 64 * ND;
            const float* Vg = Vbase + (size_t)kt * 64 * ND;
#pragma unroll
            for (int j = 0; j < 8; j++) {
                cpasync16(ks_dst + j * 16, Kg + j * 4);
                cpasync16(vs_dst + j * 16, Vg + j * 4);
            }
            CP_COMMIT();
        }

        // ---- fused threefry dropout, in the cp.async latency shadow ----
        uint32_t klo = 0u, khi = 0u;
        {
            uint32_t e0 = ebl + (uint32_t)kt * 64;
#pragma unroll 2
            for (int nt = 0; nt < 8; nt++) {
                klo |= keep2(e0 + nt * 8) << (2 * nt);
                khi |= keep2(e0 + 8u * NS + nt * 8) << (2 * nt);
            }
        }

        CP_WAIT0();
        __syncthreads();

        // ---- S = Q @ K^T ----
        float s[8][4] = {};
#pragma unroll
        for (int kc = 0; kc < 8; kc++) {
#pragma unroll
            for (int nt = 0; nt < 8; nt++) {
                uint32_t b0 = Ks[(nt * 8 + gi) * 68 + kc * 8 + ci];
                uint32_t b1 = Ks[(nt * 8 + gi) * 68 + kc * 8 + ci + 4];
                mma8(s[nt], qf[kc], b0, b1);
            }
        }

        // ---- mask + online softmax ----
        float mxl = -3.0e38f, mxh = -3.0e38f;
#pragma unroll
        for (int nt = 0; nt < 8; nt++) {
            const float* mrow = mask_lo + kt * 64 + nt * 8 + 2 * ci;
            float2 ml = *reinterpret_cast<const float2*>(mrow);
            float2 mh = *reinterpret_cast<const float2*>(mrow + 8 * NS);
            s[nt][0] += ml.x; s[nt][1] += ml.y;
            s[nt][2] += mh.x; s[nt][3] += mh.y;
            mxl = fmaxf(mxl, fmaxf(s[nt][0], s[nt][1]));
            mxh = fmaxf(mxh, fmaxf(s[nt][2], s[nt][3]));
        }
        mxl = fmaxf(mxl, __shfl_xor_sync(0xffffffffu, mxl, 1));
        mxl = fmaxf(mxl, __shfl_xor_sync(0xffffffffu, mxl, 2));
        mxh = fmaxf(mxh, __shfl_xor_sync(0xffffffffu, mxh, 1));
        mxh = fmaxf(mxh, __shfl_xor_sync(0xffffffffu, mxh, 2));

        float nml = fmaxf(m_lo, mxl), nmh = fmaxf(m_hi, mxh);
        float scl = __expf(m_lo - nml), sch = __expf(m_hi - nmh);
        m_lo = nml; m_hi = nmh;

        float suml = 0.f, sumh = 0.f;
#pragma unroll
        for (int nt = 0; nt < 8; nt++) {
            s[nt][0] = __expf(s[nt][0] - nml);
            s[nt][1] = __expf(s[nt][1] - nml);
            s[nt][2] = __expf(s[nt][2] - nmh);
            s[nt][3] = __expf(s[nt][3] - nmh);
            suml += s[nt][0] + s[nt][1];
            sumh += s[nt][2] + s[nt][3];
        }
        suml += __shfl_xor_sync(0xffffffffu, suml, 1);
        suml += __shfl_xor_sync(0xffffffffu, suml, 2);
        sumh += __shfl_xor_sync(0xffffffffu, sumh, 1);
        sumh += __shfl_xor_sync(0xffffffffu, sumh, 2);
        l_lo = l_lo * scl + suml;
        l_hi = l_hi * sch + sumh;
#pragma unroll
        for (int nt = 0; nt < 8; nt++) {
            oacc[nt][0] *= scl; oacc[nt][1] *= scl;
            oacc[nt][2] *= sch; oacc[nt][3] *= sch;
        }

        // ---- dropout apply + P store (per-warp private region) ----
        uint32_t* Pw = Ps + w * 16 * 68;
#pragma unroll
        for (int nt = 0; nt < 8; nt++) {
            int c0 = nt * 8 + 2 * ci;
            uint2 plo, phi;
            plo.x = ((klo >> (2 * nt)) & 1u)     ? f2tf32(s[nt][0]) : 0u;
            plo.y = ((klo >> (2 * nt + 1)) & 1u) ? f2tf32(s[nt][1]) : 0u;
            phi.x = ((khi >> (2 * nt)) & 1u)     ? f2tf32(s[nt][2]) : 0u;
            phi.y = ((khi >> (2 * nt + 1)) & 1u) ? f2tf32(s[nt][3]) : 0u;
            *reinterpret_cast<uint2*>(Pw + gi * 68 + c0) = plo;
            *reinterpret_cast<uint2*>(Pw + (gi + 8) * 68 + c0) = phi;
        }
        __syncwarp();

        // ---- O += P @ V ----
#pragma unroll
        for (int kc = 0; kc < 8; kc++) {
            uint32_t a[4];
            a[0] = Pw[gi * 68 + kc * 8 + ci];
            a[1] = Pw[(gi + 8) * 68 + kc * 8 + ci];
            a[2] = Pw[gi * 68 + kc * 8 + ci + 4];
            a[3] = Pw[(gi + 8) * 68 + kc * 8 + ci + 4];
#pragma unroll
            for (int nt = 0; nt < 8; nt++) {
                uint32_t b0 = Vs[(kc * 8 + ci) * 72 + nt * 8 + gi];
                uint32_t b1 = Vs[(kc * 8 + ci + 4) * 72 + nt * 8 + gi];
                mma8(oacc[nt], a, b0, b1);
            }
        }
        __syncthreads();
    }

    // epilogue: write unnormalized partial A + (m, l) per row
    float* pA = &g_pA[half][bh][rlo][0];
#pragma unroll
    for (int nt = 0; nt < 8; nt++) {
        float2 a, c;
        a.x = oacc[nt][0]; a.y = oacc[nt][1];
        c.x = oacc[nt][2]; c.y = oacc[nt][3];
        *reinterpret_cast<float2*>(pA + nt * 8 + 2 * ci) = a;
        *reinterpret_cast<float2*>(pA + 8 * ND + nt * 8 + 2 * ci) = c;
    }
    if (ci == 0) {
        g_pm[half][bh][rlo] = m_lo;     g_pl[half][bh][rlo] = l_lo;
        g_pm[half][bh][rlo + 8] = m_hi; g_pl[half][bh][rlo + 8] = l_hi;
    }
}

// ---------------------------------------------------------------------------
// Merge the two split-K halves:
//   m = max(m0,m1); l = e^{m0-m} l0 + e^{m1-m} l1
//   out = (e^{m0-m} A0 + e^{m1-m} A1) / (l * 0.9)
// One thread per 8 output columns (2x float4 per half).
// ---------------------------------------------------------------------------
__global__ void merge_kernel(float* __restrict__ out) {
    int idx = blockIdx.x * blockDim.x + threadIdx.x;   // [0, 524288)
    int rowg = idx >> 3;                 // global row [0, 65536)
    int c0 = (idx & 7) << 3;             // column start
    int bh = rowg >> 11, s = rowg & 2047;

    float m0 = g_pm[0][bh][s], m1 = g_pm[1][bh][s];
    float l0 = g_pl[0][bh][s], l1 = g_pl[1][bh][s];
    float m = fmaxf(m0, m1);
    float w0 = __expf(m0 - m), w1 = __expf(m1 - m);
    float inv = 1.0f / ((w0 * l0 + w1 * l1) * 0.9f);
    float s0 = w0 * inv, s1 = w1 * inv;

    const float4* A0 = reinterpret_cast<const float4*>(&g_pA[0][bh][s][c0]);
    const float4* A1 = reinterpret_cast<const float4*>(&g_pA[1][bh][s][c0]);
    float4* O = reinterpret_cast<float4*>(out + ((size_t)bh * NS + s) * ND + c0);
#pragma unroll
    for (int j = 0; j < 2; j++) {
        float4 a = A0[j], b = A1[j], o;
        o.x = a.x * s0 + b.x * s1;
        o.y = a.y * s0 + b.y * s1;
        o.z = a.z * s0 + b.z * s1;
        o.w = a.w * s0 + b.w * s1;
        O[j] = o;
    }
}

// ---------------------------------------------------------------------------
extern "C" void kernel_launch(void* const* d_in, const int* in_sizes, int n_in,
                              void* d_out, int out_size) {
    (void)in_sizes; (void)n_in; (void)out_size;
    const float* q   = (const float*)d_in[0];
    const float* k   = (const float*)d_in[1];
    const float* v   = (const float*)d_in[2];
    const float* msk = (const float*)d_in[3];
    const float* Wq  = (const float*)d_in[4];
    const float* bq  = (const float*)d_in[5];
    const float* Wk  = (const float*)d_in[6];
    const float* bk  = (const float*)d_in[7];
    const float* Wv  = (const float*)d_in[8];
    const float* bv  = (const float*)d_in[9];
    float* out = (float*)d_out;

    const int smem_bytes = SMEM_WORDS * 4;   // 53248 B
    cudaFuncSetAttribute(attn_mma_kernel,
                         cudaFuncAttributeMaxDynamicSharedMemorySize, smem_bytes);

    dim3 pgrid(1024, 3);
    proj_kernel<<<pgrid, 256>>>(q, k, v, Wq, Wk, Wv, bq, bk, bv);

    dim3 grid(NS / 64 * 2, NH, NB);          // qt*2 + half
    attn_mma_kernel<<<grid, 128, smem_bytes>>>(msk);

    merge_kernel<<<2048, 256>>>(out);
}

// round 15
// speedup vs baseline: 1.7633x; 1.0216x over previous
#include <cuda_runtime.h>
#include <cstdint>

#define NB 2
#define NH 16
#define NS 2048
#define ND 64
#define NSPLIT 4            /* split-K factor: 8 k-tiles per block */

// Scratch (allocation-free rule: __device__ globals)
// g_Q/g_K/g_V hold tf32-rounded bit patterns (Q pre-scaled by 1/8),
// produced by proj_kernel, consumed raw by attn (bit-identical to R5 math).
__device__ float g_Q[NB*NH*NS*ND];
__device__ float g_K[NB*NH*NS*ND];
__device__ float g_V[NB*NH*NS*ND];
// split-K partials: unnormalized A, row max m, row denom l, per quarter
__device__ float g_pA[NSPLIT][NB*NH][NS][ND];   // 67 MB
__device__ float g_pm[NSPLIT][NB*NH][NS];
__device__ float g_pl[NSPLIT][NB*NH][NS];

// ---------------------------------------------------------------------------
// helpers
// ---------------------------------------------------------------------------
__device__ __forceinline__ uint32_t f2tf32(float x) {
    uint32_t r;
    asm("cvt.rna.tf32.f32 %0, %1;" : "=r"(r) : "f"(x));
    return r;
}
// m16n8k8 tf32 warp MMA, fp32 accumulate (base ISA, works on sm_103 target)
__device__ __forceinline__ void mma8(float* c, const uint32_t* a,
                                     uint32_t b0, uint32_t b1) {
    asm volatile(
        "mma.sync.aligned.m16n8k8.row.col.f32.tf32.tf32.f32 "
        "{%0,%1,%2,%3}, {%4,%5,%6,%7}, {%8,%9}, {%0,%1,%2,%3};"
        : "+f"(c[0]), "+f"(c[1]), "+f"(c[2]), "+f"(c[3])
        : "r"(a[0]), "r"(a[1]), "r"(a[2]), "r"(a[3]), "r"(b0), "r"(b1));
}
__device__ __forceinline__ uint32_t smem_u32(const void* p) {
    uint32_t a;
    asm("{ .reg .u64 t; cvta.to.shared.u64 t, %1; cvt.u32.u64 %0, t; }"
        : "=r"(a) : "l"(p));
    return a;
}
__device__ __forceinline__ void cpasync16(uint32_t dst, const void* src) {
    asm volatile("cp.async.cg.shared.global [%0], [%1], 16;"
                 :: "r"(dst), "l"(src));
}
#define CP_COMMIT() asm volatile("cp.async.commit_group;" ::: "memory")
#define CP_WAIT0()  asm volatile("cp.async.wait_group 0;" ::: "memory")

// ---------------------------------------------------------------------------
// JAX partitionable threefry2x32, key=(0,42): bits[i] = o0^o1, counter (0,i)
// R5/R10 form (best measured). Executed between cp.async issue and wait so
// the ALU work hides the K/V GMEM->SMEM latency.
// ---------------------------------------------------------------------------
__device__ __forceinline__ uint32_t rotl32(uint32_t x, int r) {
    return __funnelshift_l(x, x, r);
}
#define KEEP_THRESH 0xE6666600u   // uniform < 0.9f, exact integer reduction

// returns bit0 = keep(e), bit1 = keep(e+1); two interleaved ciphers for ILP
__device__ __forceinline__ uint32_t keep2(uint32_t e) {
    const uint32_t k0 = 0u, k1 = 42u, k2 = 0u ^ 42u ^ 0x1BD11BDAu;
    uint32_t a0 = k0, b0 = e + k1;
    uint32_t a1 = k0, b1 = e + 1u + k1;
#define TF_R2(r) { a0 += b0; b0 = rotl32(b0, (r)) ^ a0;                        \
                   a1 += b1; b1 = rotl32(b1, (r)) ^ a1; }
    TF_R2(13) TF_R2(15) TF_R2(26) TF_R2(6)
    a0 += k1; a1 += k1; b0 += k2 + 1u; b1 += k2 + 1u;
    TF_R2(17) TF_R2(29) TF_R2(16) TF_R2(24)
    a0 += k2; a1 += k2; b0 += k0 + 2u; b1 += k0 + 2u;
    TF_R2(13) TF_R2(15) TF_R2(26) TF_R2(6)
    a0 += k0; a1 += k0; b0 += k1 + 3u; b1 += k1 + 3u;
    TF_R2(17) TF_R2(29) TF_R2(16) TF_R2(24)
    a0 += k1; a1 += k1; b0 += k2 + 4u; b1 += k2 + 4u;
    TF_R2(13) TF_R2(15) TF_R2(26) TF_R2(6)
    a0 += k2; a1 += k2; b0 += k0 + 5u; b1 += k0 + 5u;
#undef TF_R2
    uint32_t r = ((a0 ^ b0) < KEEP_THRESH) ? 1u : 0u;
    r |= ((a1 ^ b1) < KEEP_THRESH) ? 2u : 0u;
    return r;
}

// ---------------------------------------------------------------------------
// QKV projection: Y = tf32_rna(X @ W^T + b), Q additionally scaled by 1/8.
// Output [B,H,S,D]. One launch, grid.y selects {Q,K,V}.
// ---------------------------------------------------------------------------
__global__ void proj_kernel(const float* __restrict__ Xq,
                            const float* __restrict__ Xk,
                            const float* __restrict__ Xv,
                            const float* __restrict__ Wq_,
                            const float* __restrict__ Wk_,
                            const float* __restrict__ Wv_,
                            const float* __restrict__ bq_,
                            const float* __restrict__ bk_,
                            const float* __restrict__ bv_) {
    __shared__ __align__(16) float Xt[64][68];
    __shared__ __align__(16) float Wt[64][68];
    __shared__ float bs[64];
    int which = blockIdx.y;
    const float* X = (which == 0) ? Xq : (which == 1) ? Xk : Xv;
    const float* W = (which == 0) ? Wq_ : (which == 1) ? Wk_ : Wv_;
    const float* bias = (which == 0) ? bq_ : (which == 1) ? bk_ : bv_;
    float* Y = (which == 0) ? g_Q : (which == 1) ? g_K : g_V;
    float scale = (which == 0) ? 0.125f : 1.0f;

    int tid = threadIdx.x;
    if (tid < 64) bs[tid] = bias[tid];
    int r0 = blockIdx.x * 64;

#pragma unroll
    for (int r = 0; r < 4; r++) {
        int fidx = tid + r * 256;
        int row = fidx >> 4, dg = fidx & 15;
        int pg = (((row >> 2) ^ dg) << 2) + (row & 3);
        float4 w4 = reinterpret_cast<const float4*>(W)[fidx];
        Wt[4*dg+0][pg] = w4.x; Wt[4*dg+1][pg] = w4.y;
        Wt[4*dg+2][pg] = w4.z; Wt[4*dg+3][pg] = w4.w;
        float4 x4 = reinterpret_cast<const float4*>(X + (size_t)(r0 + row) * 64)[dg];
        Xt[4*dg+0][pg] = x4.x; Xt[4*dg+1][pg] = x4.y;
        Xt[4*dg+2][pg] = x4.z; Xt[4*dg+3][pg] = x4.w;
    }
    __syncthreads();

    int ty = tid >> 4, tx = tid & 15;
    float acc[4][4] = {};
#pragma unroll 8
    for (int d = 0; d < 64; d++) {
        int sw = d >> 2;
        float4 xv = *reinterpret_cast<float4*>(&Xt[d][(ty ^ sw) << 2]);
        float4 wv = *reinterpret_cast<float4*>(&Wt[d][(tx ^ sw) << 2]);
        float xa[4] = {xv.x, xv.y, xv.z, xv.w};
        float wa[4] = {wv.x, wv.y, wv.z, wv.w};
#pragma unroll
        for (int i = 0; i < 4; i++)
#pragma unroll
            for (int j = 0; j < 4; j++) acc[i][j] += xa[i] * wa[j];
    }

#pragma unroll
    for (int i = 0; i < 4; i++) {
        int r = r0 + ty * 4 + i;
        int b = r >> 15;
        int rem = r & 32767;
        int s = rem >> 4, h = rem & 15;
        uint4 o;
        o.x = f2tf32((acc[i][0] + bs[tx*4+0]) * scale);
        o.y = f2tf32((acc[i][1] + bs[tx*4+1]) * scale);
        o.z = f2tf32((acc[i][2] + bs[tx*4+2]) * scale);
        o.w = f2tf32((acc[i][3] + bs[tx*4+3]) * scale);
        reinterpret_cast<uint4*>(Y + ((size_t)(b*NH + h)*NS + s)*ND)[tx] = o;
    }
}

// ---------------------------------------------------------------------------
// Warp-MMA (m16n8k8 tf32) flash attention with FUSED threefry dropout.
// R14 body (best: 704us) with SPLIT-K = 4: each block handles 8 of 32
// k-tiles (grid.x = qt*4 + quarter), writing unnormalized partials (A,m,l);
// merge_kernel combines the four quarters. Scheduling quantum ~59us ->
// smaller wave tail (R14 validated this lever at split=2).
// Block: 64 queries x quarter x head x batch, 128 threads, 3 blocks/SM.
// SMEM (uint32): Ks [64][68], Vs [64][72], Ps [4][16][68].
// ---------------------------------------------------------------------------
#define KS_OFF 0
#define VS_OFF 4352          /* 64*68 */
#define PS_OFF 8960          /* + 64*72 */
#define SMEM_WORDS 13312     /* + 4*16*68 */

__global__ __launch_bounds__(128, 3) void attn_mma_kernel(
        const float* __restrict__ mask) {
    extern __shared__ __align__(16) uint32_t sm[];
    uint32_t* Ks = sm + KS_OFF;
    uint32_t* Vs = sm + VS_OFF;
    uint32_t* Ps = sm + PS_OFF;
    uint32_t sb = smem_u32(sm);

    int tid = threadIdx.x;
    int lane = tid & 31, w = tid >> 5;       // 4 warps
    int gi = lane >> 2, ci = lane & 3;
    int qt = blockIdx.x >> 2, quarter = blockIdx.x & 3;
    int h = blockIdx.y, b = blockIdx.z;
    int bh = b * NH + h;
    int q0 = qt * 64;
    int kt0 = quarter * (32 / NSPLIT), kt1 = kt0 + (32 / NSPLIT);

    int row = tid >> 1, hf = tid & 1;        // staging: 64 rows x 2 halves

    // staging smem byte-addresses for this thread
    uint32_t ks_dst = sb + (KS_OFF + row * 68 + hf * 32) * 4;
    uint32_t vs_dst = sb + (VS_OFF + row * 72 + hf * 32) * 4;

    // ---- stage Q tile (already tf32+scaled) into Ps via cp.async ----
    {
        uint32_t ps_dst = sb + (PS_OFF + row * 68 + hf * 32) * 4;
        const float* Qg = g_Q + ((size_t)bh * NS + q0 + row) * ND + hf * 32;
#pragma unroll
        for (int j = 0; j < 8; j++)
            cpasync16(ps_dst + j * 16, Qg + j * 4);
        CP_COMMIT();
        CP_WAIT0();
    }
    __syncthreads();
    uint32_t qf[8][4];
    {
        const uint32_t* Qs = Ps + (w * 16) * 68;
#pragma unroll
        for (int kc = 0; kc < 8; kc++) {
            qf[kc][0] = Qs[gi * 68 + kc * 8 + ci];
            qf[kc][1] = Qs[(gi + 8) * 68 + kc * 8 + ci];
            qf[kc][2] = Qs[gi * 68 + kc * 8 + ci + 4];
            qf[kc][3] = Qs[(gi + 8) * 68 + kc * 8 + ci + 4];
        }
    }
    __syncthreads();   // Ps will be overwritten as P-buffer in the mainloop

    float oacc[8][4] = {};
    float m_lo = -3.0e38f, m_hi = -3.0e38f, l_lo = 0.f, l_hi = 0.f;

    int rlo = q0 + w * 16 + gi;              // rhi = rlo + 8 (derived)
    const float* mask_lo = mask + ((size_t)b * NS + rlo) * NS;
    // flat dropout-element base (hi base = lo + 8*NS, constant)
    uint32_t ebl = (uint32_t)(bh * NS + rlo) * NS + 2 * ci;

    const float* Kbase = g_K + ((size_t)bh * NS + row) * ND + hf * 32;
    const float* Vbase = g_V + ((size_t)bh * NS + row) * ND + hf * 32;

    for (int kt = kt0; kt < kt1; kt++) {
        // ---- issue K,V tile copies (GMEM -> SMEM, no registers) ----
        {
            const float* Kg = Kbase + (size_t)kt * 64 * ND;
            const float* Vg = Vbase + (size_t)kt * 64 * ND;
#pragma unroll
            for (int j = 0; j < 8; j++) {
                cpasync16(ks_dst + j * 16, Kg + j * 4);
                cpasync16(vs_dst + j * 16, Vg + j * 4);
            }
            CP_COMMIT();
        }

        // ---- fused threefry dropout, in the cp.async latency shadow ----
        uint32_t klo = 0u, khi = 0u;
        {
            uint32_t e0 = ebl + (uint32_t)kt * 64;
#pragma unroll 2
            for (int nt = 0; nt < 8; nt++) {
                klo |= keep2(e0 + nt * 8) << (2 * nt);
                khi |= keep2(e0 + 8u * NS + nt * 8) << (2 * nt);
            }
        }

        CP_WAIT0();
        __syncthreads();

        // ---- S = Q @ K^T ----
        float s[8][4] = {};
#pragma unroll
        for (int kc = 0; kc < 8; kc++) {
#pragma unroll
            for (int nt = 0; nt < 8; nt++) {
                uint32_t b0 = Ks[(nt * 8 + gi) * 68 + kc * 8 + ci];
                uint32_t b1 = Ks[(nt * 8 + gi) * 68 + kc * 8 + ci + 4];
                mma8(s[nt], qf[kc], b0, b1);
            }
        }

        // ---- mask + online softmax ----
        float mxl = -3.0e38f, mxh = -3.0e38f;
#pragma unroll
        for (int nt = 0; nt < 8; nt++) {
            const float* mrow = mask_lo + kt * 64 + nt * 8 + 2 * ci;
            float2 ml = *reinterpret_cast<const float2*>(mrow);
            float2 mh = *reinterpret_cast<const float2*>(mrow + 8 * NS);
            s[nt][0] += ml.x; s[nt][1] += ml.y;
            s[nt][2] += mh.x; s[nt][3] += mh.y;
            mxl = fmaxf(mxl, fmaxf(s[nt][0], s[nt][1]));
            mxh = fmaxf(mxh, fmaxf(s[nt][2], s[nt][3]));
        }
        mxl = fmaxf(mxl, __shfl_xor_sync(0xffffffffu, mxl, 1));
        mxl = fmaxf(mxl, __shfl_xor_sync(0xffffffffu, mxl, 2));
        mxh = fmaxf(mxh, __shfl_xor_sync(0xffffffffu, mxh, 1));
        mxh = fmaxf(mxh, __shfl_xor_sync(0xffffffffu, mxh, 2));

        float nml = fmaxf(m_lo, mxl), nmh = fmaxf(m_hi, mxh);
        float scl = __expf(m_lo - nml), sch = __expf(m_hi - nmh);
        m_lo = nml; m_hi = nmh;

        float suml = 0.f, sumh = 0.f;
#pragma unroll
        for (int nt = 0; nt < 8; nt++) {
            s[nt][0] = __expf(s[nt][0] - nml);
            s[nt][1] = __expf(s[nt][1] - nml);
            s[nt][2] = __expf(s[nt][2] - nmh);
            s[nt][3] = __expf(s[nt][3] - nmh);
            suml += s[nt][0] + s[nt][1];
            sumh += s[nt][2] + s[nt][3];
        }
        suml += __shfl_xor_sync(0xffffffffu, suml, 1);
        suml += __shfl_xor_sync(0xffffffffu, suml, 2);
        sumh += __shfl_xor_sync(0xffffffffu, sumh, 1);
        sumh += __shfl_xor_sync(0xffffffffu, sumh, 2);
        l_lo = l_lo * scl + suml;
        l_hi = l_hi * sch + sumh;
#pragma unroll
        for (int nt = 0; nt < 8; nt++) {
            oacc[nt][0] *= scl; oacc[nt][1] *= scl;
            oacc[nt][2] *= sch; oacc[nt][3] *= sch;
        }

        // ---- dropout apply + P store (per-warp private region) ----
        uint32_t* Pw = Ps + w * 16 * 68;
#pragma unroll
        for (int nt = 0; nt < 8; nt++) {
            int c0 = nt * 8 + 2 * ci;
            uint2 plo, phi;
            plo.x = ((klo >> (2 * nt)) & 1u)     ? f2tf32(s[nt][0]) : 0u;
            plo.y = ((klo >> (2 * nt + 1)) & 1u) ? f2tf32(s[nt][1]) : 0u;
            phi.x = ((khi >> (2 * nt)) & 1u)     ? f2tf32(s[nt][2]) : 0u;
            phi.y = ((khi >> (2 * nt + 1)) & 1u) ? f2tf32(s[nt][3]) : 0u;
            *reinterpret_cast<uint2*>(Pw + gi * 68 + c0) = plo;
            *reinterpret_cast<uint2*>(Pw + (gi + 8) * 68 + c0) = phi;
        }
        __syncwarp();

        // ---- O += P @ V ----
#pragma unroll
        for (int kc = 0; kc < 8; kc++) {
            uint32_t a[4];
            a[0] = Pw[gi * 68 + kc * 8 + ci];
            a[1] = Pw[(gi + 8) * 68 + kc * 8 + ci];
            a[2] = Pw[gi * 68 + kc * 8 + ci + 4];
            a[3] = Pw[(gi + 8) * 68 + kc * 8 + ci + 4];
#pragma unroll
            for (int nt = 0; nt < 8; nt++) {
                uint32_t b0 = Vs[(kc * 8 + ci) * 72 + nt * 8 + gi];
                uint32_t b1 = Vs[(kc * 8 + ci + 4) * 72 + nt * 8 + gi];
                mma8(oacc[nt], a, b0, b1);
            }
        }
        __syncthreads();
    }

    // epilogue: write unnormalized partial A + (m, l) per row
    float* pA = &g_pA[quarter][bh][rlo][0];
#pragma unroll
    for (int nt = 0; nt < 8; nt++) {
        float2 a, c;
        a.x = oacc[nt][0]; a.y = oacc[nt][1];
        c.x = oacc[nt][2]; c.y = oacc[nt][3];
        *reinterpret_cast<float2*>(pA + nt * 8 + 2 * ci) = a;
        *reinterpret_cast<float2*>(pA + 8 * ND + nt * 8 + 2 * ci) = c;
    }
    if (ci == 0) {
        g_pm[quarter][bh][rlo] = m_lo;     g_pl[quarter][bh][rlo] = l_lo;
        g_pm[quarter][bh][rlo + 8] = m_hi; g_pl[quarter][bh][rlo + 8] = l_hi;
    }
}

// ---------------------------------------------------------------------------
// Merge the four split-K quarters:
//   m = max_i m_i; w_i = e^{m_i-m}; l = sum w_i l_i
//   out = (sum w_i A_i) / (l * 0.9)
// One thread per 8 output columns (2x float4 per quarter).
// ---------------------------------------------------------------------------
__global__ void merge_kernel(float* __restrict__ out) {
    int idx = blockIdx.x * blockDim.x + threadIdx.x;   // [0, 524288)
    int rowg = idx >> 3;                 // global row [0, 65536)
    int c0 = (idx & 7) << 3;             // column start
    int bh = rowg >> 11, s = rowg & 2047;

    float m = -3.0e38f;
#pragma unroll
    for (int i = 0; i < NSPLIT; i++) m = fmaxf(m, g_pm[i][bh][s]);
    float wgt[NSPLIT], lsum = 0.f;
#pragma unroll
    for (int i = 0; i < NSPLIT; i++) {
        wgt[i] = __expf(g_pm[i][bh][s] - m);
        lsum += wgt[i] * g_pl[i][bh][s];
    }
    float inv = 1.0f / (lsum * 0.9f);

    float4* O = reinterpret_cast<float4*>(out + ((size_t)bh * NS + s) * ND + c0);
#pragma unroll
    for (int j = 0; j < 2; j++) {
        float4 o = make_float4(0.f, 0.f, 0.f, 0.f);
#pragma unroll
        for (int i = 0; i < NSPLIT; i++) {
            float4 a = reinterpret_cast<const float4*>(&g_pA[i][bh][s][c0])[j];
            float sc = wgt[i] * inv;
            o.x += a.x * sc; o.y += a.y * sc;
            o.z += a.z * sc; o.w += a.w * sc;
        }
        O[j] = o;
    }
}

// ---------------------------------------------------------------------------
extern "C" void kernel_launch(void* const* d_in, const int* in_sizes, int n_in,
                              void* d_out, int out_size) {
    (void)in_sizes; (void)n_in; (void)out_size;
    const float* q   = (const float*)d_in[0];
    const float* k   = (const float*)d_in[1];
    const float* v   = (const float*)d_in[2];
    const float* msk = (const float*)d_in[3];
    const float* Wq  = (const float*)d_in[4];
    const float* bq  = (const float*)d_in[5];
    const float* Wk  = (const float*)d_in[6];
    const float* bk  = (const float*)d_in[7];
    const float* Wv  = (const float*)d_in[8];
    const float* bv  = (const float*)d_in[9];
    float* out = (float*)d_out;

    const int smem_bytes = SMEM_WORDS * 4;   // 53248 B
    cudaFuncSetAttribute(attn_mma_kernel,
                         cudaFuncAttributeMaxDynamicSharedMemorySize, smem_bytes);

    dim3 pgrid(1024, 3);
    proj_kernel<<<pgrid, 256>>>(q, k, v, Wq, Wk, Wv, bq, bk, bv);

    dim3 grid(NS / 64 * NSPLIT, NH, NB);     // qt*4 + quarter
    attn_mma_kernel<<<grid, 128, smem_bytes>>>(msk);

    merge_kernel<<<2048, 256>>>(out);
}